// round 1
// baseline (speedup 1.0000x reference)
#include <cuda_runtime.h>
#include <math.h>

// ---------------- problem constants ----------------
#define BATCH 2
#define GRD 28          // grid D=H=W
#define CDIM 96
#define NHEAD 3
#define HDIM 32
#define WSZ 7
#define NTOK 343        // 7^3 tokens per window
#define NBW 4           // windows per axis (28/7)
#define NWIN 64         // windows per batch
#define BN (BATCH*NWIN) // 128 total windows
#define TOK (BATCH*GRD*GRD*GRD)   // 43904 tokens
#define QKVO (3*CDIM)   // 288
#define FF (4*CDIM)     // 384
#define NBIAS 2197      // 13^3
#define SCALE 0.17677669529663687f  // 32^-0.5

// ---------------- scratch buffers ----------------
__device__ float g_x   [TOK*CDIM];   // residual stream
__device__ float g_xw  [TOK*CDIM];   // LN1 + windowed
__device__ float g_qkv [TOK*QKVO];
__device__ float g_aout[TOK*CDIM];
__device__ float g_xn  [TOK*CDIM];   // LN2
__device__ float g_h1  [TOK*FF];

// ---------------- copy ----------------
__global__ void copyk(const float4* __restrict__ s, float4* __restrict__ d, int n) {
    for (int i = blockIdx.x*blockDim.x + threadIdx.x; i < n; i += gridDim.x*blockDim.x)
        d[i] = s[i];
}

// ---------------- LN1 + shift + window partition ----------------
// one warp per window-token; gathers from x at (coord+3)%28 when shifted
__global__ __launch_bounds__(128) void ln_part_kernel(
    const float* __restrict__ x, float* __restrict__ xw,
    const float* __restrict__ gamma, const float* __restrict__ beta, int shifted)
{
    int warp = threadIdx.x >> 5, lane = threadIdx.x & 31;
    int g = blockIdx.x*4 + warp;              // 0..43903
    int win = g / NTOK, n = g % NTOK;
    int b = win >> 6, wrem = win & 63;
    int bd = wrem >> 4, bh = (wrem >> 2) & 3, bw = wrem & 3;
    int ld = n / 49, rr = n % 49, lh = rr / 7, lw = rr % 7;
    int d = bd*7 + ld, h = bh*7 + lh, w = bw*7 + lw;
    if (shifted) {
        d += 3; if (d >= GRD) d -= GRD;
        h += 3; if (h >= GRD) h -= GRD;
        w += 3; if (w >= GRD) w -= GRD;
    }
    size_t row = (size_t)(((b*GRD + d)*GRD + h)*GRD + w) * CDIM;
    float v0 = x[row + lane], v1 = x[row + 32 + lane], v2 = x[row + 64 + lane];
    float s = v0 + v1 + v2;
    #pragma unroll
    for (int off = 16; off; off >>= 1) s += __shfl_xor_sync(0xffffffffu, s, off);
    float mean = s * (1.f/96.f);
    float d0 = v0-mean, d1 = v1-mean, d2 = v2-mean;
    float ss = d0*d0 + d1*d1 + d2*d2;
    #pragma unroll
    for (int off = 16; off; off >>= 1) ss += __shfl_xor_sync(0xffffffffu, ss, off);
    float rstd = rsqrtf(ss * (1.f/96.f) + 1e-5f);
    size_t orow = (size_t)g * CDIM;
    xw[orow + lane]      = d0*rstd*gamma[lane]    + beta[lane];
    xw[orow + 32 + lane] = d1*rstd*gamma[32+lane] + beta[32+lane];
    xw[orow + 64 + lane] = d2*rstd*gamma[64+lane] + beta[64+lane];
}

// ---------------- LN2 (plain layout) ----------------
__global__ __launch_bounds__(128) void ln2_kernel(
    const float* __restrict__ x, float* __restrict__ xn,
    const float* __restrict__ gamma, const float* __restrict__ beta)
{
    int warp = threadIdx.x >> 5, lane = threadIdx.x & 31;
    int g = blockIdx.x*4 + warp;
    size_t row = (size_t)g * CDIM;
    float v0 = x[row + lane], v1 = x[row + 32 + lane], v2 = x[row + 64 + lane];
    float s = v0 + v1 + v2;
    #pragma unroll
    for (int off = 16; off; off >>= 1) s += __shfl_xor_sync(0xffffffffu, s, off);
    float mean = s * (1.f/96.f);
    float d0 = v0-mean, d1 = v1-mean, d2 = v2-mean;
    float ss = d0*d0 + d1*d1 + d2*d2;
    #pragma unroll
    for (int off = 16; off; off >>= 1) ss += __shfl_xor_sync(0xffffffffu, ss, off);
    float rstd = rsqrtf(ss * (1.f/96.f) + 1e-5f);
    xn[row + lane]      = d0*rstd*gamma[lane]    + beta[lane];
    xn[row + 32 + lane] = d1*rstd*gamma[32+lane] + beta[32+lane];
    xn[row + 64 + lane] = d2*rstd*gamma[64+lane] + beta[64+lane];
}

// ---------------- generic GEMM: Y[M,O] = epi(X[M,K] @ W[O,K]^T + b) ----------------
// tile 64x64, 256 threads, 4x4 microtile, smem stored [k][m] with stride 68
#define KT 96
#define LDSS 68
#define GEMM_SMEM (2*KT*LDSS*sizeof(float))

#define EPI_STORE 0
#define EPI_PROJ  1   // window-reverse + unshift + residual add into xres
#define EPI_GELU  2
#define EPI_RES   3   // residual add into xres (plain layout, O==96)

template<int EPI>
__global__ __launch_bounds__(256) void gemm_kernel(
    const float* __restrict__ X, const float* __restrict__ W,
    const float* __restrict__ bias, float* __restrict__ Y,
    float* __restrict__ xres, int Kdim, int O, int shifted)
{
    extern __shared__ float sh[];
    float* Xs = sh;
    float* Ws = sh + KT*LDSS;
    int m0 = blockIdx.x * 64, o0 = blockIdx.y * 64;
    int tid = threadIdx.x;
    int tm = (tid & 15) * 4, to = (tid >> 4) * 4;
    float acc[4][4] = {};

    for (int kc = 0; kc < Kdim; kc += KT) {
        for (int e = tid; e < KT*64; e += 256) {
            int m = e / KT, k = e % KT;
            Xs[k*LDSS + m] = X[(size_t)(m0 + m)*Kdim + kc + k];
            int orow = o0 + m;
            Ws[k*LDSS + m] = (orow < O) ? W[(size_t)orow*Kdim + kc + k] : 0.f;
        }
        __syncthreads();
        #pragma unroll 8
        for (int k = 0; k < KT; k++) {
            float4 a  = *(const float4*)(Xs + k*LDSS + tm);
            float4 bv = *(const float4*)(Ws + k*LDSS + to);
            float av[4] = {a.x, a.y, a.z, a.w};
            float bb[4] = {bv.x, bv.y, bv.z, bv.w};
            #pragma unroll
            for (int i = 0; i < 4; i++)
                #pragma unroll
                for (int j = 0; j < 4; j++)
                    acc[i][j] += av[i]*bb[j];
        }
        __syncthreads();
    }

    #pragma unroll
    for (int i = 0; i < 4; i++) {
        int m = m0 + tm + i;
        size_t drow = 0;
        if (EPI == EPI_PROJ) {
            int win = m / NTOK, n = m % NTOK;
            int b = win >> 6, wrem = win & 63;
            int bd = wrem >> 4, bh = (wrem >> 2) & 3, bw = wrem & 3;
            int ld = n / 49, rr = n % 49, lh = rr / 7, lw = rr % 7;
            int d = bd*7 + ld, h = bh*7 + lh, w = bw*7 + lw;
            if (shifted) {
                d += 3; if (d >= GRD) d -= GRD;
                h += 3; if (h >= GRD) h -= GRD;
                w += 3; if (w >= GRD) w -= GRD;
            }
            drow = (size_t)(((b*GRD + d)*GRD + h)*GRD + w) * CDIM;
        }
        #pragma unroll
        for (int j = 0; j < 4; j++) {
            int o = o0 + to + j;
            if (o < O) {
                float v = acc[i][j] + bias[o];
                if (EPI == EPI_STORE) {
                    Y[(size_t)m*O + o] = v;
                } else if (EPI == EPI_PROJ) {
                    xres[drow + o] += v;
                } else if (EPI == EPI_GELU) {
                    Y[(size_t)m*O + o] = 0.5f*v*(1.f + erff(v*0.70710678118654752f));
                } else { // EPI_RES
                    xres[(size_t)m*CDIM + o] += v;
                }
            }
        }
    }
}

// ---------------- attention: one block per (window, head) ----------------
#define ATTN_SMEM (2*NTOK*HDIM*sizeof(float))

__global__ __launch_bounds__(128) void attn_kernel(
    const float* __restrict__ qkv, float* __restrict__ aout,
    const float* __restrict__ relb, int shifted)
{
    extern __shared__ float sh[];
    float* Ks = sh;
    float* Vs = sh + NTOK*HDIM;
    int bx = blockIdx.x;
    int win = bx / NHEAD, head = bx % NHEAD;
    int base = win * NTOK;
    int tid = threadIdx.x;
    int qoff = head * HDIM;

    for (int idx = tid; idx < NTOK*HDIM; idx += 128) {
        int j = idx >> 5, d = idx & 31;
        const float* row = qkv + (size_t)(base + j) * QKVO;
        Ks[idx] = row[CDIM   + qoff + d];
        Vs[idx] = row[2*CDIM + qoff + d];
    }
    __syncthreads();

    int wrem = win & 63;
    int bd = wrem >> 4, bh = (wrem >> 2) & 3, bw = wrem & 3;

    for (int qi = tid; qi < NTOK; qi += 128) {
        float q[32];
        const float* qrow = qkv + (size_t)(base + qi) * QKVO + qoff;
        #pragma unroll
        for (int d = 0; d < 32; d++) q[d] = qrow[d] * SCALE;
        int di = qi / 49, rem = qi % 49, hi = rem / 7, wi = rem % 7;
        int regi = 0;
        if (shifted) {
            int rd = (bd == 3) ? ((di < 4) ? 1 : 2) : 0;
            int rh = (bh == 3) ? ((hi < 4) ? 1 : 2) : 0;
            int rw = (bw == 3) ? ((wi < 4) ? 1 : 2) : 0;
            regi = rd*9 + rh*3 + rw;
        }
        float mval = -1e30f, l = 0.f;
        float o[32];
        #pragma unroll
        for (int d = 0; d < 32; d++) o[d] = 0.f;

        int j = 0;
        for (int dj = 0; dj < 7; dj++) {
            int ib0 = (di - dj + 6) * 169;
            int rdj = (shifted && bd == 3) ? ((dj < 4) ? 1 : 2) : 0;
            for (int hj = 0; hj < 7; hj++) {
                int ib1 = ib0 + (hi - hj + 6) * 13;
                int rhj = (shifted && bh == 3) ? ((hj < 4) ? 1 : 2) : 0;
                for (int wj = 0; wj < 7; wj++, j++) {
                    const float4* kr = (const float4*)(Ks + j*32);
                    float s = 0.f;
                    #pragma unroll
                    for (int t = 0; t < 8; t++) {
                        float4 kv = kr[t];
                        s += q[4*t]*kv.x + q[4*t+1]*kv.y + q[4*t+2]*kv.z + q[4*t+3]*kv.w;
                    }
                    int bidx = ib1 + (wi - wj + 6);
                    s += relb[bidx*NHEAD + head];
                    if (shifted) {
                        int rwj = (bw == 3) ? ((wj < 4) ? 1 : 2) : 0;
                        if ((rdj*9 + rhj*3 + rwj) != regi) s -= 100.f;
                    }
                    float mn = fmaxf(mval, s);
                    float al = __expf(mval - mn);
                    float p  = __expf(s - mn);
                    l = l*al + p;
                    mval = mn;
                    const float4* vr = (const float4*)(Vs + j*32);
                    #pragma unroll
                    for (int t = 0; t < 8; t++) {
                        float4 vv = vr[t];
                        o[4*t]   = o[4*t]*al   + p*vv.x;
                        o[4*t+1] = o[4*t+1]*al + p*vv.y;
                        o[4*t+2] = o[4*t+2]*al + p*vv.z;
                        o[4*t+3] = o[4*t+3]*al + p*vv.w;
                    }
                }
            }
        }
        float inv = 1.f / l;
        float* orow = aout + (size_t)(base + qi) * CDIM + qoff;
        #pragma unroll
        for (int d = 0; d < 32; d++) orow[d] = o[d] * inv;
    }
}

// ---------------- launch ----------------
extern "C" void kernel_launch(void* const* d_in, const int* in_sizes, int n_in,
                              void* d_out, int out_size)
{
    const float* x_in   = (const float*)d_in[0];
    const float* n1g    = (const float*)d_in[1];
    const float* n1b    = (const float*)d_in[2];
    const float* qkvw   = (const float*)d_in[3];
    const float* qkvb   = (const float*)d_in[4];
    const float* relb   = (const float*)d_in[5];
    const float* projw  = (const float*)d_in[6];
    const float* projb  = (const float*)d_in[7];
    const float* n2g    = (const float*)d_in[8];
    const float* n2b    = (const float*)d_in[9];
    const float* fc1w   = (const float*)d_in[10];
    const float* fc1b   = (const float*)d_in[11];
    const float* fc2w   = (const float*)d_in[12];
    const float* fc2b   = (const float*)d_in[13];
    float* out = (float*)d_out;

    float *px, *pxw, *pqkv, *paout, *pxn, *ph1;
    cudaGetSymbolAddress((void**)&px,    g_x);
    cudaGetSymbolAddress((void**)&pxw,   g_xw);
    cudaGetSymbolAddress((void**)&pqkv,  g_qkv);
    cudaGetSymbolAddress((void**)&paout, g_aout);
    cudaGetSymbolAddress((void**)&pxn,   g_xn);
    cudaGetSymbolAddress((void**)&ph1,   g_h1);

    cudaFuncSetAttribute(gemm_kernel<EPI_STORE>, cudaFuncAttributeMaxDynamicSharedMemorySize, GEMM_SMEM);
    cudaFuncSetAttribute(gemm_kernel<EPI_PROJ>,  cudaFuncAttributeMaxDynamicSharedMemorySize, GEMM_SMEM);
    cudaFuncSetAttribute(gemm_kernel<EPI_GELU>,  cudaFuncAttributeMaxDynamicSharedMemorySize, GEMM_SMEM);
    cudaFuncSetAttribute(gemm_kernel<EPI_RES>,   cudaFuncAttributeMaxDynamicSharedMemorySize, GEMM_SMEM);
    cudaFuncSetAttribute(attn_kernel,            cudaFuncAttributeMaxDynamicSharedMemorySize, ATTN_SMEM);

    int n4 = TOK*CDIM/4;
    copyk<<<1024, 256>>>((const float4*)x_in, (float4*)px, n4);

    const int MB = TOK/64;     // 686 exact
    for (int L = 0; L < 2; L++) {
        int shifted = L & 1;
        ln_part_kernel<<<TOK/4, 128>>>(px, pxw, n1g + L*CDIM, n1b + L*CDIM, shifted);
        gemm_kernel<EPI_STORE><<<dim3(MB, (QKVO+63)/64), 256, GEMM_SMEM>>>(
            pxw, qkvw + (size_t)L*QKVO*CDIM, qkvb + L*QKVO, pqkv, nullptr, CDIM, QKVO, 0);
        attn_kernel<<<BN*NHEAD, 128, ATTN_SMEM>>>(pqkv, paout, relb + (size_t)L*NBIAS*NHEAD, shifted);
        gemm_kernel<EPI_PROJ><<<dim3(MB, (CDIM+63)/64), 256, GEMM_SMEM>>>(
            paout, projw + (size_t)L*CDIM*CDIM, projb + L*CDIM, nullptr, px, CDIM, CDIM, shifted);
        ln2_kernel<<<TOK/4, 128>>>(px, pxn, n2g + L*CDIM, n2b + L*CDIM);
        gemm_kernel<EPI_GELU><<<dim3(MB, (FF+63)/64), 256, GEMM_SMEM>>>(
            pxn, fc1w + (size_t)L*FF*CDIM, fc1b + L*FF, ph1, nullptr, CDIM, FF, 0);
        gemm_kernel<EPI_RES><<<dim3(MB, (CDIM+63)/64), 256, GEMM_SMEM>>>(
            ph1, fc2w + (size_t)L*CDIM*FF, fc2b + L*CDIM, nullptr, px, FF, CDIM, 0);
    }

    copyk<<<1024, 256>>>((const float4*)px, (float4*)out, n4);
}

// round 4
// speedup vs baseline: 2.0316x; 2.0316x over previous
#include <cuda_runtime.h>
#include <math.h>

// ---------------- problem constants ----------------
#define BATCH 2
#define GRD 28
#define CDIM 96
#define NHEAD 3
#define HDIM 32
#define NTOK 343
#define NWIN 64
#define BN (BATCH*NWIN)
#define TOK (BATCH*GRD*GRD*GRD)   // 43904
#define QKVO (3*CDIM)   // 288
#define FF (4*CDIM)     // 384
#define NBIAS 2197
#define SCALE 0.17677669529663687f

// ---------------- scratch buffers ----------------
__device__ float g_x   [TOK*CDIM];
__device__ float g_xw  [TOK*CDIM];
__device__ float g_qkv [TOK*QKVO];
__device__ float g_aout[TOK*CDIM];
__device__ float g_xn  [TOK*CDIM];
__device__ float g_h1  [TOK*FF];

// ---------------- copy ----------------
__global__ void copyk(const float4* __restrict__ s, float4* __restrict__ d, int n) {
    for (int i = blockIdx.x*blockDim.x + threadIdx.x; i < n; i += gridDim.x*blockDim.x)
        d[i] = s[i];
}

// ---------------- LN1 + shift + window partition ----------------
__global__ __launch_bounds__(128) void ln_part_kernel(
    const float* __restrict__ x, float* __restrict__ xw,
    const float* __restrict__ gamma, const float* __restrict__ beta, int shifted)
{
    int warp = threadIdx.x >> 5, lane = threadIdx.x & 31;
    int g = blockIdx.x*4 + warp;
    int win = g / NTOK, n = g % NTOK;
    int b = win >> 6, wrem = win & 63;
    int bd = wrem >> 4, bh = (wrem >> 2) & 3, bw = wrem & 3;
    int ld = n / 49, rr = n % 49, lh = rr / 7, lw = rr % 7;
    int d = bd*7 + ld, h = bh*7 + lh, w = bw*7 + lw;
    if (shifted) {
        d += 3; if (d >= GRD) d -= GRD;
        h += 3; if (h >= GRD) h -= GRD;
        w += 3; if (w >= GRD) w -= GRD;
    }
    size_t row = (size_t)(((b*GRD + d)*GRD + h)*GRD + w) * CDIM;
    float v0 = x[row + lane], v1 = x[row + 32 + lane], v2 = x[row + 64 + lane];
    float s = v0 + v1 + v2;
    #pragma unroll
    for (int off = 16; off; off >>= 1) s += __shfl_xor_sync(0xffffffffu, s, off);
    float mean = s * (1.f/96.f);
    float d0 = v0-mean, d1 = v1-mean, d2 = v2-mean;
    float ss = d0*d0 + d1*d1 + d2*d2;
    #pragma unroll
    for (int off = 16; off; off >>= 1) ss += __shfl_xor_sync(0xffffffffu, ss, off);
    float rstd = rsqrtf(ss * (1.f/96.f) + 1e-5f);
    size_t orow = (size_t)g * CDIM;
    xw[orow + lane]      = d0*rstd*gamma[lane]    + beta[lane];
    xw[orow + 32 + lane] = d1*rstd*gamma[32+lane] + beta[32+lane];
    xw[orow + 64 + lane] = d2*rstd*gamma[64+lane] + beta[64+lane];
}

// ---------------- LN2 ----------------
__global__ __launch_bounds__(128) void ln2_kernel(
    const float* __restrict__ x, float* __restrict__ xn,
    const float* __restrict__ gamma, const float* __restrict__ beta)
{
    int warp = threadIdx.x >> 5, lane = threadIdx.x & 31;
    int g = blockIdx.x*4 + warp;
    size_t row = (size_t)g * CDIM;
    float v0 = x[row + lane], v1 = x[row + 32 + lane], v2 = x[row + 64 + lane];
    float s = v0 + v1 + v2;
    #pragma unroll
    for (int off = 16; off; off >>= 1) s += __shfl_xor_sync(0xffffffffu, s, off);
    float mean = s * (1.f/96.f);
    float d0 = v0-mean, d1 = v1-mean, d2 = v2-mean;
    float ss = d0*d0 + d1*d1 + d2*d2;
    #pragma unroll
    for (int off = 16; off; off >>= 1) ss += __shfl_xor_sync(0xffffffffu, ss, off);
    float rstd = rsqrtf(ss * (1.f/96.f) + 1e-5f);
    xn[row + lane]      = d0*rstd*gamma[lane]    + beta[lane];
    xn[row + 32 + lane] = d1*rstd*gamma[32+lane] + beta[32+lane];
    xn[row + 64 + lane] = d2*rstd*gamma[64+lane] + beta[64+lane];
}

// ---------------- GEMM: Y[M,O] = epi(X[M,K] @ W[O,K]^T + b) ----------------
// tile 128x96, 256 threads, microtile 8x6, K-chunk 96
#define LDX 132
#define LDW 100
#define GEMM_SMEM ((96*LDX + 96*LDW)*sizeof(float))  // 89088 B

#define EPI_STORE 0
#define EPI_PROJ  1
#define EPI_GELU  2
#define EPI_RES   3

template<int EPI>
__global__ __launch_bounds__(256, 2) void gemm_kernel(
    const float* __restrict__ X, const float* __restrict__ W,
    const float* __restrict__ bias, float* __restrict__ Y,
    float* __restrict__ xres, int Kdim, int O, int shifted)
{
    extern __shared__ float sh[];
    float* Xs = sh;
    float* Ws = sh + 96*LDX;
    int m0 = blockIdx.x * 128, o0 = blockIdx.y * 96;
    int tid = threadIdx.x;
    int mt = (tid & 15) * 4, ot = (tid >> 4) * 6;
    float acc[8][6];
    #pragma unroll
    for (int i = 0; i < 8; i++)
        #pragma unroll
        for (int j = 0; j < 6; j++) acc[i][j] = 0.f;

    for (int kc = 0; kc < Kdim; kc += 96) {
        if (kc) __syncthreads();
        #pragma unroll
        for (int i = 0; i < 12; i++) {
            int e = tid + i*256;
            int m = e / 24, kq = e % 24;
            float4 v = *(const float4*)(X + (size_t)(m0+m)*Kdim + kc + 4*kq);
            float* p = Xs + 4*kq*LDX + m;
            p[0]=v.x; p[LDX]=v.y; p[2*LDX]=v.z; p[3*LDX]=v.w;
        }
        #pragma unroll
        for (int i = 0; i < 9; i++) {
            int e = tid + i*256;
            int m = e / 24, kq = e % 24;
            float4 v = *(const float4*)(W + (size_t)(o0+m)*Kdim + kc + 4*kq);
            float* p = Ws + 4*kq*LDW + m;
            p[0]=v.x; p[LDW]=v.y; p[2*LDW]=v.z; p[3*LDW]=v.w;
        }
        __syncthreads();
        #pragma unroll 8
        for (int k = 0; k < 96; k++) {
            float4 a0 = *(const float4*)(Xs + k*LDX + mt);
            float4 a1 = *(const float4*)(Xs + k*LDX + mt + 64);
            float2 b0 = *(const float2*)(Ws + k*LDW + ot);
            float2 b1 = *(const float2*)(Ws + k*LDW + ot + 2);
            float2 b2 = *(const float2*)(Ws + k*LDW + ot + 4);
            float av[8] = {a0.x,a0.y,a0.z,a0.w,a1.x,a1.y,a1.z,a1.w};
            float bv[6] = {b0.x,b0.y,b1.x,b1.y,b2.x,b2.y};
            #pragma unroll
            for (int i = 0; i < 8; i++)
                #pragma unroll
                for (int j = 0; j < 6; j++)
                    acc[i][j] += av[i]*bv[j];
        }
    }

    #pragma unroll
    for (int i = 0; i < 8; i++) {
        int m = m0 + ((i < 4) ? (mt + i) : (64 + mt + i - 4));
        size_t drow = 0;
        if (EPI == EPI_PROJ) {
            int win = m / NTOK, n = m % NTOK;
            int b = win >> 6, wrem = win & 63;
            int bd = wrem >> 4, bh = (wrem >> 2) & 3, bw = wrem & 3;
            int ld = n / 49, rr = n % 49, lh = rr / 7, lw = rr % 7;
            int d = bd*7 + ld, h = bh*7 + lh, w = bw*7 + lw;
            if (shifted) {
                d += 3; if (d >= GRD) d -= GRD;
                h += 3; if (h >= GRD) h -= GRD;
                w += 3; if (w >= GRD) w -= GRD;
            }
            drow = (size_t)(((b*GRD + d)*GRD + h)*GRD + w) * CDIM;
        }
        #pragma unroll
        for (int j = 0; j < 6; j++) {
            int o = o0 + ot + j;
            float v = acc[i][j] + bias[o];
            if (EPI == EPI_STORE) {
                Y[(size_t)m*O + o] = v;
            } else if (EPI == EPI_PROJ) {
                xres[drow + o] += v;
            } else if (EPI == EPI_GELU) {
                Y[(size_t)m*O + o] = 0.5f*v*(1.f + erff(v*0.70710678118654752f));
            } else {
                xres[(size_t)m*CDIM + o] += v;
            }
        }
    }
}

// ---------------- attention ----------------
// grid (BN*NHEAD, 3): blockIdx.y = qi pass. K/V staged in 2 smem chunks
// (dj planes 0..3 = 196 keys, 4..6 = 147 keys): smem 50KB -> 4 CTAs/SM.
#define CH0 196
#define ATTN_SMEM (2*CH0*HDIM*sizeof(float))

__global__ __launch_bounds__(128, 4) void attn_kernel(
    const float* __restrict__ qkv, float* __restrict__ aout,
    const float* __restrict__ relb, int shifted)
{
    extern __shared__ float sh[];
    float* Ks = sh;
    float* Vs = sh + CH0*HDIM;
    int bx = blockIdx.x;
    int win = bx / NHEAD, head = bx % NHEAD;
    int base = win * NTOK;
    int tid = threadIdx.x;
    int qoff = head * HDIM;

    int wrem = win & 63;
    int bd = wrem >> 4, bh = (wrem >> 2) & 3, bw = wrem & 3;

    int qi = blockIdx.y * 128 + tid;
    bool act = qi < NTOK;
    float q[32], o[32];
    float mval = -1e30f, l = 0.f;
    int di = 0, hi = 0, wi = 0, regi = 0;
    if (act) {
        const float4* qrow = (const float4*)(qkv + (size_t)(base + qi)*QKVO + qoff);
        #pragma unroll
        for (int t = 0; t < 8; t++) {
            float4 v = qrow[t];
            q[4*t] = v.x*SCALE; q[4*t+1] = v.y*SCALE; q[4*t+2] = v.z*SCALE; q[4*t+3] = v.w*SCALE;
        }
        di = qi / 49; int rem = qi % 49; hi = rem / 7; wi = rem % 7;
        if (shifted) {
            int rd = (bd == 3) ? ((di < 4) ? 1 : 2) : 0;
            int rh = (bh == 3) ? ((hi < 4) ? 1 : 2) : 0;
            int rw = (bw == 3) ? ((wi < 4) ? 1 : 2) : 0;
            regi = rd*9 + rh*3 + rw;
        }
        #pragma unroll
        for (int d = 0; d < 32; d++) o[d] = 0.f;
    }

    int j0 = 0;
    for (int ch = 0; ch < 2; ch++) {
        int cnt = ch ? (NTOK - CH0) : CH0;
        if (ch) __syncthreads();
        for (int idx = tid; idx < cnt*8; idx += 128) {
            int j = idx >> 3, dq = idx & 7;
            const float4* row = (const float4*)(qkv + (size_t)(base + j0 + j)*QKVO + qoff);
            ((float4*)Ks)[j*8 + dq] = row[CDIM/4 + dq];       // K: +96 floats + dq*4
            ((float4*)Vs)[j*8 + dq] = row[2*CDIM/4 + dq];     // V: +192 floats + dq*4
        }
        __syncthreads();
        if (act) {
            int j = 0;
            int dlo = ch ? 4 : 0, dhi = ch ? 7 : 4;
            for (int dj = dlo; dj < dhi; dj++) {
                int ib0 = (di - dj + 6) * 169;
                int rdj = (shifted && bd == 3) ? ((dj < 4) ? 1 : 2) : 0;
                for (int hj = 0; hj < 7; hj++) {
                    int ib1 = ib0 + (hi - hj + 6) * 13;
                    int rhj = (shifted && bh == 3) ? ((hj < 4) ? 1 : 2) : 0;
                    for (int wj = 0; wj < 7; wj++, j++) {
                        const float4* kr = (const float4*)(Ks + j*32);
                        float s = 0.f;
                        #pragma unroll
                        for (int t = 0; t < 8; t++) {
                            float4 kv = kr[t];
                            s += q[4*t]*kv.x + q[4*t+1]*kv.y + q[4*t+2]*kv.z + q[4*t+3]*kv.w;
                        }
                        int bidx = ib1 + (wi - wj + 6);
                        s += relb[bidx*NHEAD + head];
                        if (shifted) {
                            int rwj = (bw == 3) ? ((wj < 4) ? 1 : 2) : 0;
                            if ((rdj*9 + rhj*3 + rwj) != regi) s -= 100.f;
                        }
                        float mn = fmaxf(mval, s);
                        float al = __expf(mval - mn);
                        float p  = __expf(s - mn);
                        l = l*al + p;
                        mval = mn;
                        const float4* vr = (const float4*)(Vs + j*32);
                        #pragma unroll
                        for (int t = 0; t < 8; t++) {
                            float4 vv = vr[t];
                            o[4*t]   = o[4*t]*al   + p*vv.x;
                            o[4*t+1] = o[4*t+1]*al + p*vv.y;
                            o[4*t+2] = o[4*t+2]*al + p*vv.z;
                            o[4*t+3] = o[4*t+3]*al + p*vv.w;
                        }
                    }
                }
            }
        }
        j0 += cnt;
    }
    if (act) {
        float inv = 1.f / l;
        float4* orow = (float4*)(aout + (size_t)(base + qi)*CDIM + qoff);
        #pragma unroll
        for (int t = 0; t < 8; t++) {
            float4 v;
            v.x = o[4*t]*inv; v.y = o[4*t+1]*inv; v.z = o[4*t+2]*inv; v.w = o[4*t+3]*inv;
            orow[t] = v;
        }
    }
}

// ---------------- launch ----------------
extern "C" void kernel_launch(void* const* d_in, const int* in_sizes, int n_in,
                              void* d_out, int out_size)
{
    const float* x_in   = (const float*)d_in[0];
    const float* n1g    = (const float*)d_in[1];
    const float* n1b    = (const float*)d_in[2];
    const float* qkvw   = (const float*)d_in[3];
    const float* qkvb   = (const float*)d_in[4];
    const float* relb   = (const float*)d_in[5];
    const float* projw  = (const float*)d_in[6];
    const float* projb  = (const float*)d_in[7];
    const float* n2g    = (const float*)d_in[8];
    const float* n2b    = (const float*)d_in[9];
    const float* fc1w   = (const float*)d_in[10];
    const float* fc1b   = (const float*)d_in[11];
    const float* fc2w   = (const float*)d_in[12];
    const float* fc2b   = (const float*)d_in[13];
    float* out = (float*)d_out;

    float *px, *pxw, *pqkv, *paout, *pxn, *ph1;
    cudaGetSymbolAddress((void**)&px,    g_x);
    cudaGetSymbolAddress((void**)&pxw,   g_xw);
    cudaGetSymbolAddress((void**)&pqkv,  g_qkv);
    cudaGetSymbolAddress((void**)&paout, g_aout);
    cudaGetSymbolAddress((void**)&pxn,   g_xn);
    cudaGetSymbolAddress((void**)&ph1,   g_h1);

    cudaFuncSetAttribute(gemm_kernel<EPI_STORE>, cudaFuncAttributeMaxDynamicSharedMemorySize, GEMM_SMEM);
    cudaFuncSetAttribute(gemm_kernel<EPI_PROJ>,  cudaFuncAttributeMaxDynamicSharedMemorySize, GEMM_SMEM);
    cudaFuncSetAttribute(gemm_kernel<EPI_GELU>,  cudaFuncAttributeMaxDynamicSharedMemorySize, GEMM_SMEM);
    cudaFuncSetAttribute(gemm_kernel<EPI_RES>,   cudaFuncAttributeMaxDynamicSharedMemorySize, GEMM_SMEM);
    cudaFuncSetAttribute(attn_kernel,            cudaFuncAttributeMaxDynamicSharedMemorySize, ATTN_SMEM);

    int n4 = TOK*CDIM/4;
    copyk<<<1024, 256>>>((const float4*)x_in, (float4*)px, n4);

    const int MB = TOK/128;   // 343 exact
    for (int L = 0; L < 2; L++) {
        int shifted = L & 1;
        ln_part_kernel<<<TOK/4, 128>>>(px, pxw, n1g + L*CDIM, n1b + L*CDIM, shifted);
        gemm_kernel<EPI_STORE><<<dim3(MB, QKVO/96), 256, GEMM_SMEM>>>(
            pxw, qkvw + (size_t)L*QKVO*CDIM, qkvb + L*QKVO, pqkv, nullptr, CDIM, QKVO, 0);
        attn_kernel<<<dim3(BN*NHEAD, 3), 128, ATTN_SMEM>>>(
            pqkv, paout, relb + (size_t)L*NBIAS*NHEAD, shifted);
        gemm_kernel<EPI_PROJ><<<dim3(MB, 1), 256, GEMM_SMEM>>>(
            paout, projw + (size_t)L*CDIM*CDIM, projb + L*CDIM, nullptr, px, CDIM, CDIM, shifted);
        ln2_kernel<<<TOK/4, 128>>>(px, pxn, n2g + L*CDIM, n2b + L*CDIM);
        gemm_kernel<EPI_GELU><<<dim3(MB, FF/96), 256, GEMM_SMEM>>>(
            pxn, fc1w + (size_t)L*FF*CDIM, fc1b + L*FF, ph1, nullptr, CDIM, FF, 0);
        gemm_kernel<EPI_RES><<<dim3(MB, 1), 256, GEMM_SMEM>>>(
            ph1, fc2w + (size_t)L*CDIM*FF, fc2b + L*CDIM, nullptr, px, FF, CDIM, 0);
    }

    copyk<<<1024, 256>>>((const float4*)px, (float4*)out, n4);
}

// round 6
// speedup vs baseline: 3.2516x; 1.6005x over previous
#include <cuda_runtime.h>
#include <cuda_bf16.h>
#include <math.h>
#include <stdint.h>

// ---------------- problem constants ----------------
#define BATCH 2
#define GRD 28
#define CDIM 96
#define NHEAD 3
#define HDIM 32
#define NTOK 343
#define NWIN 64
#define BN (BATCH*NWIN)
#define TOK (BATCH*GRD*GRD*GRD)   // 43904
#define QKVO (3*CDIM)   // 288
#define FF (4*CDIM)     // 384
#define NBIAS 2197
#define SCALE 0.17677669529663687f

// ---------------- scratch buffers ----------------
__device__ float g_x   [TOK*CDIM];
__device__ float g_xw  [TOK*CDIM];
__device__ float g_qkv [TOK*QKVO];
__device__ float g_aout[TOK*CDIM];
__device__ float g_xn  [TOK*CDIM];
__device__ float g_h1  [TOK*FF];

// ---------------- helpers ----------------
__device__ __forceinline__ uint32_t smem_u32(const void* p) {
    uint32_t a;
    asm("{ .reg .u64 t; cvta.to.shared.u64 t, %1; cvt.u32.u64 %0, t; }" : "=r"(a) : "l"(p));
    return a;
}
__device__ __forceinline__ void ldsm4(uint32_t* r, uint32_t addr) {
    asm volatile("ldmatrix.sync.aligned.m8n8.x4.shared.b16 {%0,%1,%2,%3}, [%4];"
        : "=r"(r[0]), "=r"(r[1]), "=r"(r[2]), "=r"(r[3]) : "r"(addr));
}
__device__ __forceinline__ void mma16816(float* c, const uint32_t* a, const uint32_t* b) {
    asm volatile("mma.sync.aligned.m16n8k16.row.col.f32.bf16.bf16.f32 "
        "{%0,%1,%2,%3}, {%4,%5,%6,%7}, {%8,%9}, {%0,%1,%2,%3};"
        : "+f"(c[0]), "+f"(c[1]), "+f"(c[2]), "+f"(c[3])
        : "r"(a[0]), "r"(a[1]), "r"(a[2]), "r"(a[3]), "r"(b[0]), "r"(b[1]));
}

// ---------------- copy ----------------
__global__ void copyk(const float4* __restrict__ s, float4* __restrict__ d, int n) {
    for (int i = blockIdx.x*blockDim.x + threadIdx.x; i < n; i += gridDim.x*blockDim.x)
        d[i] = s[i];
}

// ---------------- LN1 + shift + window partition ----------------
__global__ __launch_bounds__(128) void ln_part_kernel(
    const float* __restrict__ x, float* __restrict__ xw,
    const float* __restrict__ gamma, const float* __restrict__ beta, int shifted)
{
    int warp = threadIdx.x >> 5, lane = threadIdx.x & 31;
    int g = blockIdx.x*4 + warp;
    int win = g / NTOK, n = g % NTOK;
    int b = win >> 6, wrem = win & 63;
    int bd = wrem >> 4, bh = (wrem >> 2) & 3, bw = wrem & 3;
    int ld = n / 49, rr = n % 49, lh = rr / 7, lw = rr % 7;
    int d = bd*7 + ld, h = bh*7 + lh, w = bw*7 + lw;
    if (shifted) {
        d += 3; if (d >= GRD) d -= GRD;
        h += 3; if (h >= GRD) h -= GRD;
        w += 3; if (w >= GRD) w -= GRD;
    }
    size_t row = (size_t)(((b*GRD + d)*GRD + h)*GRD + w) * CDIM;
    float v0 = x[row + lane], v1 = x[row + 32 + lane], v2 = x[row + 64 + lane];
    float s = v0 + v1 + v2;
    #pragma unroll
    for (int off = 16; off; off >>= 1) s += __shfl_xor_sync(0xffffffffu, s, off);
    float mean = s * (1.f/96.f);
    float d0 = v0-mean, d1 = v1-mean, d2 = v2-mean;
    float ss = d0*d0 + d1*d1 + d2*d2;
    #pragma unroll
    for (int off = 16; off; off >>= 1) ss += __shfl_xor_sync(0xffffffffu, ss, off);
    float rstd = rsqrtf(ss * (1.f/96.f) + 1e-5f);
    size_t orow = (size_t)g * CDIM;
    xw[orow + lane]      = d0*rstd*gamma[lane]    + beta[lane];
    xw[orow + 32 + lane] = d1*rstd*gamma[32+lane] + beta[32+lane];
    xw[orow + 64 + lane] = d2*rstd*gamma[64+lane] + beta[64+lane];
}

// ---------------- LN2 ----------------
__global__ __launch_bounds__(128) void ln2_kernel(
    const float* __restrict__ x, float* __restrict__ xn,
    const float* __restrict__ gamma, const float* __restrict__ beta)
{
    int warp = threadIdx.x >> 5, lane = threadIdx.x & 31;
    int g = blockIdx.x*4 + warp;
    size_t row = (size_t)g * CDIM;
    float v0 = x[row + lane], v1 = x[row + 32 + lane], v2 = x[row + 64 + lane];
    float s = v0 + v1 + v2;
    #pragma unroll
    for (int off = 16; off; off >>= 1) s += __shfl_xor_sync(0xffffffffu, s, off);
    float mean = s * (1.f/96.f);
    float d0 = v0-mean, d1 = v1-mean, d2 = v2-mean;
    float ss = d0*d0 + d1*d1 + d2*d2;
    #pragma unroll
    for (int off = 16; off; off >>= 1) ss += __shfl_xor_sync(0xffffffffu, ss, off);
    float rstd = rsqrtf(ss * (1.f/96.f) + 1e-5f);
    xn[row + lane]      = d0*rstd*gamma[lane]    + beta[lane];
    xn[row + 32 + lane] = d1*rstd*gamma[32+lane] + beta[32+lane];
    xn[row + 64 + lane] = d2*rstd*gamma[64+lane] + beta[64+lane];
}

// ---------------- HMMA GEMM: Y[M,O] = epi(X[M,K] @ W[O,K]^T + b) ----------------
// block tile 128x96, 8 warps (warp tile 32x48), mma.m16n8k16 bf16.
// fp32 -> bf16 hi/lo split, D = Ah*Bh + Ah*Bl + Al*Bh (fp32 accum in regs).
// smem: padded row-major bf16, ld = 104 elements (ldmatrix conflict-free).
#define LDB 104
#define A_HI 0
#define A_LO 26624
#define B_HI 53248
#define B_LO 73216
#define TC_SMEM 93184

#define EPI_STORE 0
#define EPI_PROJ  1
#define EPI_GELU  2
#define EPI_RES   3

__device__ __forceinline__ void split_pack(float a, float b, uint32_t& hi, uint32_t& lo) {
    __nv_bfloat16 ha = __float2bfloat16_rn(a), hb = __float2bfloat16_rn(b);
    float ra = a - __bfloat162float(ha), rb = b - __bfloat162float(hb);
    __nv_bfloat162 h = __halves2bfloat162(ha, hb);
    __nv_bfloat162 l = __halves2bfloat162(__float2bfloat16_rn(ra), __float2bfloat16_rn(rb));
    hi = *(uint32_t*)&h;
    lo = *(uint32_t*)&l;
}

template<int EPI>
__global__ __launch_bounds__(256) void tc_gemm(
    const float* __restrict__ X, const float* __restrict__ W,
    const float* __restrict__ bias, float* __restrict__ Y,
    float* __restrict__ xres, int Kdim, int O, int shifted)
{
    extern __shared__ char smem[];
    uint32_t sb = smem_u32(smem);
    int tid = threadIdx.x, wid = tid >> 5, lane = tid & 31;
    int m0 = blockIdx.x * 128, o0 = blockIdx.y * 96;
    int wm = (wid & 3) * 32, wn = (wid >> 2) * 48;

    float acc[2][6][4];
    #pragma unroll
    for (int i = 0; i < 2; i++)
        #pragma unroll
        for (int j = 0; j < 6; j++)
            #pragma unroll
            for (int t = 0; t < 4; t++) acc[i][j][t] = 0.f;

    int nch = Kdim / 96;
    for (int ch = 0; ch < nch; ch++) {
        int kc = ch * 96;
        if (ch) __syncthreads();
        // ---- stage A (128 x 96) hi/lo ----
        #pragma unroll
        for (int i = 0; i < 12; i++) {
            int e = tid + i*256;
            int m = e / 24, k = (e % 24) * 4;
            float4 v = *(const float4*)(X + (size_t)(m0 + m)*Kdim + kc + k);
            uint32_t h0, l0, h1, l1;
            split_pack(v.x, v.y, h0, l0);
            split_pack(v.z, v.w, h1, l1);
            uint32_t off = (uint32_t)(m*LDB + k)*2;
            *(uint2*)(smem + A_HI + off) = make_uint2(h0, h1);
            *(uint2*)(smem + A_LO + off) = make_uint2(l0, l1);
        }
        // ---- stage B (96 x 96) hi/lo ----
        #pragma unroll
        for (int i = 0; i < 9; i++) {
            int e = tid + i*256;
            int r = e / 24, k = (e % 24) * 4;
            float4 v = *(const float4*)(W + (size_t)(o0 + r)*Kdim + kc + k);
            uint32_t h0, l0, h1, l1;
            split_pack(v.x, v.y, h0, l0);
            split_pack(v.z, v.w, h1, l1);
            uint32_t off = (uint32_t)(r*LDB + k)*2;
            *(uint2*)(smem + B_HI + off) = make_uint2(h0, h1);
            *(uint2*)(smem + B_LO + off) = make_uint2(l0, l1);
        }
        __syncthreads();

        #pragma unroll
        for (int pass = 0; pass < 3; pass++) {
            uint32_t abase = sb + (pass == 2 ? A_LO : A_HI);
            uint32_t bbase = sb + (pass == 1 ? B_LO : B_HI);
            #pragma unroll
            for (int ks = 0; ks < 6; ks++) {
                int k = ks * 16;
                uint32_t af[2][4];
                #pragma unroll
                for (int mf = 0; mf < 2; mf++) {
                    int r = wm + mf*16 + (lane & 15);
                    int c = k + ((lane >> 4) << 3);
                    ldsm4(af[mf], abase + (uint32_t)(r*LDB + c)*2);
                }
                uint32_t bf[6][2];
                #pragma unroll
                for (int nq = 0; nq < 3; nq++) {
                    int r = wn + nq*16 + (lane & 7) + ((lane >> 4) << 3);
                    int c = k + (((lane >> 3) & 1) << 3);
                    uint32_t t[4];
                    ldsm4(t, bbase + (uint32_t)(r*LDB + c)*2);
                    bf[nq*2][0] = t[0];  bf[nq*2][1] = t[1];
                    bf[nq*2+1][0] = t[2]; bf[nq*2+1][1] = t[3];
                }
                #pragma unroll
                for (int mf = 0; mf < 2; mf++)
                    #pragma unroll
                    for (int nf = 0; nf < 6; nf++)
                        mma16816(acc[mf][nf], af[mf], bf[nf]);
            }
        }
    }
    __syncthreads();

    // ---- epilogue: frags -> smem (fp32, +bias) -> coalesced global ----
    float* Dsm = (float*)smem;
    #pragma unroll
    for (int mf = 0; mf < 2; mf++) {
        int row = wm + mf*16 + (lane >> 2);
        #pragma unroll
        for (int nf = 0; nf < 6; nf++) {
            int col = wn + nf*8 + (lane & 3)*2;
            float b0 = bias[o0 + col], b1 = bias[o0 + col + 1];
            Dsm[row*100 + col]       = acc[mf][nf][0] + b0;
            Dsm[row*100 + col + 1]   = acc[mf][nf][1] + b1;
            Dsm[(row+8)*100 + col]   = acc[mf][nf][2] + b0;
            Dsm[(row+8)*100 + col+1] = acc[mf][nf][3] + b1;
        }
    }
    __syncthreads();
    #pragma unroll
    for (int i = 0; i < 12; i++) {
        int e = tid + i*256;
        int m = e / 24, c = (e % 24) * 4;
        float4 v = *(const float4*)(Dsm + m*100 + c);
        int gm = m0 + m, o = o0 + c;
        if (EPI == EPI_STORE) {
            *(float4*)(Y + (size_t)gm*O + o) = v;
        } else if (EPI == EPI_GELU) {
            v.x = 0.5f*v.x*(1.f + erff(v.x*0.70710678118654752f));
            v.y = 0.5f*v.y*(1.f + erff(v.y*0.70710678118654752f));
            v.z = 0.5f*v.z*(1.f + erff(v.z*0.70710678118654752f));
            v.w = 0.5f*v.w*(1.f + erff(v.w*0.70710678118654752f));
            *(float4*)(Y + (size_t)gm*O + o) = v;
        } else if (EPI == EPI_RES) {
            float4 r = *(const float4*)(xres + (size_t)gm*CDIM + o);
            r.x += v.x; r.y += v.y; r.z += v.z; r.w += v.w;
            *(float4*)(xres + (size_t)gm*CDIM + o) = r;
        } else { // EPI_PROJ
            int win = gm / NTOK, n = gm % NTOK;
            int b = win >> 6, wrem = win & 63;
            int bd = wrem >> 4, bh = (wrem >> 2) & 3, bw = wrem & 3;
            int ld = n / 49, rr2 = n % 49, lh = rr2 / 7, lw = rr2 % 7;
            int d = bd*7 + ld, h = bh*7 + lh, w = bw*7 + lw;
            if (shifted) {
                d += 3; if (d >= GRD) d -= GRD;
                h += 3; if (h >= GRD) h -= GRD;
                w += 3; if (w >= GRD) w -= GRD;
            }
            size_t drow = (size_t)(((b*GRD + d)*GRD + h)*GRD + w) * CDIM;
            float4 r = *(const float4*)(xres + drow + o);
            r.x += v.x; r.y += v.y; r.z += v.z; r.w += v.w;
            *(float4*)(xres + drow + o) = r;
        }
    }
}

// ---------------- attention ----------------
#define CH0 196
#define ATTN_SMEM (2*CH0*HDIM*sizeof(float))

__global__ __launch_bounds__(128, 4) void attn_kernel(
    const float* __restrict__ qkv, float* __restrict__ aout,
    const float* __restrict__ relb, int shifted)
{
    extern __shared__ float sh[];
    float* Ks = sh;
    float* Vs = sh + CH0*HDIM;
    int bx = blockIdx.x;
    int win = bx / NHEAD, head = bx % NHEAD;
    int base = win * NTOK;
    int tid = threadIdx.x;
    int qoff = head * HDIM;

    int wrem = win & 63;
    int bd = wrem >> 4, bh = (wrem >> 2) & 3, bw = wrem & 3;

    int qi = blockIdx.y * 128 + tid;
    bool act = qi < NTOK;
    float q[32], o[32];
    float mval = -1e30f, l = 0.f;
    int di = 0, hi = 0, wi = 0, regi = 0;
    if (act) {
        const float4* qrow = (const float4*)(qkv + (size_t)(base + qi)*QKVO + qoff);
        #pragma unroll
        for (int t = 0; t < 8; t++) {
            float4 v = qrow[t];
            q[4*t] = v.x*SCALE; q[4*t+1] = v.y*SCALE; q[4*t+2] = v.z*SCALE; q[4*t+3] = v.w*SCALE;
        }
        di = qi / 49; int rem = qi % 49; hi = rem / 7; wi = rem % 7;
        if (shifted) {
            int rd = (bd == 3) ? ((di < 4) ? 1 : 2) : 0;
            int rh = (bh == 3) ? ((hi < 4) ? 1 : 2) : 0;
            int rw = (bw == 3) ? ((wi < 4) ? 1 : 2) : 0;
            regi = rd*9 + rh*3 + rw;
        }
        #pragma unroll
        for (int d = 0; d < 32; d++) o[d] = 0.f;
    }

    int j0 = 0;
    for (int ch = 0; ch < 2; ch++) {
        int cnt = ch ? (NTOK - CH0) : CH0;
        if (ch) __syncthreads();
        for (int idx = tid; idx < cnt*8; idx += 128) {
            int j = idx >> 3, dq = idx & 7;
            const float4* row = (const float4*)(qkv + (size_t)(base + j0 + j)*QKVO + qoff);
            ((float4*)Ks)[j*8 + dq] = row[CDIM/4 + dq];
            ((float4*)Vs)[j*8 + dq] = row[2*CDIM/4 + dq];
        }
        __syncthreads();
        if (act) {
            int j = 0;
            int dlo = ch ? 4 : 0, dhi = ch ? 7 : 4;
            for (int dj = dlo; dj < dhi; dj++) {
                int ib0 = (di - dj + 6) * 169;
                int rdj = (shifted && bd == 3) ? ((dj < 4) ? 1 : 2) : 0;
                for (int hj = 0; hj < 7; hj++) {
                    int ib1 = ib0 + (hi - hj + 6) * 13;
                    int rhj = (shifted && bh == 3) ? ((hj < 4) ? 1 : 2) : 0;
                    for (int wj = 0; wj < 7; wj++, j++) {
                        const float4* kr = (const float4*)(Ks + j*32);
                        float s = 0.f;
                        #pragma unroll
                        for (int t = 0; t < 8; t++) {
                            float4 kv = kr[t];
                            s += q[4*t]*kv.x + q[4*t+1]*kv.y + q[4*t+2]*kv.z + q[4*t+3]*kv.w;
                        }
                        int bidx = ib1 + (wi - wj + 6);
                        s += relb[bidx*NHEAD + head];
                        if (shifted) {
                            int rwj = (bw == 3) ? ((wj < 4) ? 1 : 2) : 0;
                            if ((rdj*9 + rhj*3 + rwj) != regi) s -= 100.f;
                        }
                        const float4* vr = (const float4*)(Vs + j*32);
                        if (s <= mval) {
                            float p = __expf(s - mval);
                            l += p;
                            #pragma unroll
                            for (int t = 0; t < 8; t++) {
                                float4 vv = vr[t];
                                o[4*t]   += p*vv.x; o[4*t+1] += p*vv.y;
                                o[4*t+2] += p*vv.z; o[4*t+3] += p*vv.w;
                            }
                        } else {
                            float al = __expf(mval - s);
                            mval = s;
                            l = l*al + 1.f;
                            #pragma unroll
                            for (int t = 0; t < 8; t++) {
                                float4 vv = vr[t];
                                o[4*t]   = o[4*t]*al   + vv.x;
                                o[4*t+1] = o[4*t+1]*al + vv.y;
                                o[4*t+2] = o[4*t+2]*al + vv.z;
                                o[4*t+3] = o[4*t+3]*al + vv.w;
                            }
                        }
                    }
                }
            }
        }
        j0 += cnt;
    }
    if (act) {
        float inv = 1.f / l;
        float4* orow = (float4*)(aout + (size_t)(base + qi)*CDIM + qoff);
        #pragma unroll
        for (int t = 0; t < 8; t++) {
            float4 v;
            v.x = o[4*t]*inv; v.y = o[4*t+1]*inv; v.z = o[4*t+2]*inv; v.w = o[4*t+3]*inv;
            orow[t] = v;
        }
    }
}

// ---------------- launch ----------------
extern "C" void kernel_launch(void* const* d_in, const int* in_sizes, int n_in,
                              void* d_out, int out_size)
{
    const float* x_in   = (const float*)d_in[0];
    const float* n1g    = (const float*)d_in[1];
    const float* n1b    = (const float*)d_in[2];
    const float* qkvw   = (const float*)d_in[3];
    const float* qkvb   = (const float*)d_in[4];
    const float* relb   = (const float*)d_in[5];
    const float* projw  = (const float*)d_in[6];
    const float* projb  = (const float*)d_in[7];
    const float* n2g    = (const float*)d_in[8];
    const float* n2b    = (const float*)d_in[9];
    const float* fc1w   = (const float*)d_in[10];
    const float* fc1b   = (const float*)d_in[11];
    const float* fc2w   = (const float*)d_in[12];
    const float* fc2b   = (const float*)d_in[13];
    float* out = (float*)d_out;

    float *px, *pxw, *pqkv, *paout, *pxn, *ph1;
    cudaGetSymbolAddress((void**)&px,    g_x);
    cudaGetSymbolAddress((void**)&pxw,   g_xw);
    cudaGetSymbolAddress((void**)&pqkv,  g_qkv);
    cudaGetSymbolAddress((void**)&paout, g_aout);
    cudaGetSymbolAddress((void**)&pxn,   g_xn);
    cudaGetSymbolAddress((void**)&ph1,   g_h1);

    cudaFuncSetAttribute(tc_gemm<EPI_STORE>, cudaFuncAttributeMaxDynamicSharedMemorySize, TC_SMEM);
    cudaFuncSetAttribute(tc_gemm<EPI_PROJ>,  cudaFuncAttributeMaxDynamicSharedMemorySize, TC_SMEM);
    cudaFuncSetAttribute(tc_gemm<EPI_GELU>,  cudaFuncAttributeMaxDynamicSharedMemorySize, TC_SMEM);
    cudaFuncSetAttribute(tc_gemm<EPI_RES>,   cudaFuncAttributeMaxDynamicSharedMemorySize, TC_SMEM);
    cudaFuncSetAttribute(attn_kernel,        cudaFuncAttributeMaxDynamicSharedMemorySize, ATTN_SMEM);

    int n4 = TOK*CDIM/4;
    copyk<<<1024, 256>>>((const float4*)x_in, (float4*)px, n4);

    const int MB = TOK/128;   // 343 exact
    for (int L = 0; L < 2; L++) {
        int shifted = L & 1;
        ln_part_kernel<<<TOK/4, 128>>>(px, pxw, n1g + L*CDIM, n1b + L*CDIM, shifted);
        tc_gemm<EPI_STORE><<<dim3(MB, QKVO/96), 256, TC_SMEM>>>(
            pxw, qkvw + (size_t)L*QKVO*CDIM, qkvb + L*QKVO, pqkv, nullptr, CDIM, QKVO, 0);
        attn_kernel<<<dim3(BN*NHEAD, 3), 128, ATTN_SMEM>>>(
            pqkv, paout, relb + (size_t)L*NBIAS*NHEAD, shifted);
        tc_gemm<EPI_PROJ><<<dim3(MB, 1), 256, TC_SMEM>>>(
            paout, projw + (size_t)L*CDIM*CDIM, projb + L*CDIM, nullptr, px, CDIM, CDIM, shifted);
        ln2_kernel<<<TOK/4, 128>>>(px, pxn, n2g + L*CDIM, n2b + L*CDIM);
        tc_gemm<EPI_GELU><<<dim3(MB, FF/96), 256, TC_SMEM>>>(
            pxn, fc1w + (size_t)L*FF*CDIM, fc1b + L*FF, ph1, nullptr, CDIM, FF, 0);
        tc_gemm<EPI_RES><<<dim3(MB, 1), 256, TC_SMEM>>>(
            ph1, fc2w + (size_t)L*CDIM*FF, fc2b + L*CDIM, nullptr, px, FF, CDIM, 0);
    }

    copyk<<<1024, 256>>>((const float4*)px, (float4*)out, n4);
}

// round 7
// speedup vs baseline: 3.5009x; 1.0767x over previous
#include <cuda_runtime.h>
#include <cuda_fp16.h>
#include <math.h>
#include <stdint.h>

// ---------------- problem constants ----------------
#define BATCH 2
#define GRD 28
#define CDIM 96
#define NHEAD 3
#define HDIM 32
#define NTOK 343
#define NWIN 64
#define BN (BATCH*NWIN)
#define TOK (BATCH*GRD*GRD*GRD)   // 43904
#define QKVO (3*CDIM)   // 288
#define FF (4*CDIM)     // 384
#define NBIAS 2197
#define SCALE 0.17677669529663687f

// ---------------- scratch buffers ----------------
__device__ float g_x   [TOK*CDIM];
__device__ float g_xw  [TOK*CDIM];
__device__ float g_qkv [TOK*QKVO];
__device__ float g_aout[TOK*CDIM];
__device__ float g_xn  [TOK*CDIM];
__device__ float g_h1  [TOK*FF];
__device__ float g_bm  [24*NTOK*NTOK + 16];   // bias+mask matrices [head*8+cls][343][343]

// ---------------- helpers ----------------
__device__ __forceinline__ uint32_t smem_u32(const void* p) {
    uint32_t a;
    asm("{ .reg .u64 t; cvta.to.shared.u64 t, %1; cvt.u32.u64 %0, t; }" : "=r"(a) : "l"(p));
    return a;
}
__device__ __forceinline__ void ldsm4(uint32_t* r, uint32_t addr) {
    asm volatile("ldmatrix.sync.aligned.m8n8.x4.shared.b16 {%0,%1,%2,%3}, [%4];"
        : "=r"(r[0]), "=r"(r[1]), "=r"(r[2]), "=r"(r[3]) : "r"(addr));
}
__device__ __forceinline__ void mma_fp16(float* c, const uint32_t* a, const uint32_t* b) {
    asm volatile("mma.sync.aligned.m16n8k16.row.col.f32.f16.f16.f32 "
        "{%0,%1,%2,%3}, {%4,%5,%6,%7}, {%8,%9}, {%0,%1,%2,%3};"
        : "+f"(c[0]), "+f"(c[1]), "+f"(c[2]), "+f"(c[3])
        : "r"(a[0]), "r"(a[1]), "r"(a[2]), "r"(a[3]), "r"(b[0]), "r"(b[1]));
}
__device__ __forceinline__ uint32_t packh2(float a, float b) {
    half2 h = __floats2half2_rn(a, b);
    return *(uint32_t*)&h;
}

// ---------------- copy ----------------
__global__ void copyk(const float4* __restrict__ s, float4* __restrict__ d, int n) {
    for (int i = blockIdx.x*blockDim.x + threadIdx.x; i < n; i += gridDim.x*blockDim.x)
        d[i] = s[i];
}

// ---------------- LN1 + shift + window partition ----------------
__global__ __launch_bounds__(128) void ln_part_kernel(
    const float* __restrict__ x, float* __restrict__ xw,
    const float* __restrict__ gamma, const float* __restrict__ beta, int shifted)
{
    int warp = threadIdx.x >> 5, lane = threadIdx.x & 31;
    int g = blockIdx.x*4 + warp;
    int win = g / NTOK, n = g % NTOK;
    int b = win >> 6, wrem = win & 63;
    int bd = wrem >> 4, bh = (wrem >> 2) & 3, bw = wrem & 3;
    int ld = n / 49, rr = n % 49, lh = rr / 7, lw = rr % 7;
    int d = bd*7 + ld, h = bh*7 + lh, w = bw*7 + lw;
    if (shifted) {
        d += 3; if (d >= GRD) d -= GRD;
        h += 3; if (h >= GRD) h -= GRD;
        w += 3; if (w >= GRD) w -= GRD;
    }
    size_t row = (size_t)(((b*GRD + d)*GRD + h)*GRD + w) * CDIM;
    float v0 = x[row + lane], v1 = x[row + 32 + lane], v2 = x[row + 64 + lane];
    float s = v0 + v1 + v2;
    #pragma unroll
    for (int off = 16; off; off >>= 1) s += __shfl_xor_sync(0xffffffffu, s, off);
    float mean = s * (1.f/96.f);
    float d0 = v0-mean, d1 = v1-mean, d2 = v2-mean;
    float ss = d0*d0 + d1*d1 + d2*d2;
    #pragma unroll
    for (int off = 16; off; off >>= 1) ss += __shfl_xor_sync(0xffffffffu, ss, off);
    float rstd = rsqrtf(ss * (1.f/96.f) + 1e-5f);
    size_t orow = (size_t)g * CDIM;
    xw[orow + lane]      = d0*rstd*gamma[lane]    + beta[lane];
    xw[orow + 32 + lane] = d1*rstd*gamma[32+lane] + beta[32+lane];
    xw[orow + 64 + lane] = d2*rstd*gamma[64+lane] + beta[64+lane];
}

// ---------------- LN2 ----------------
__global__ __launch_bounds__(128) void ln2_kernel(
    const float* __restrict__ x, float* __restrict__ xn,
    const float* __restrict__ gamma, const float* __restrict__ beta)
{
    int warp = threadIdx.x >> 5, lane = threadIdx.x & 31;
    int g = blockIdx.x*4 + warp;
    size_t row = (size_t)g * CDIM;
    float v0 = x[row + lane], v1 = x[row + 32 + lane], v2 = x[row + 64 + lane];
    float s = v0 + v1 + v2;
    #pragma unroll
    for (int off = 16; off; off >>= 1) s += __shfl_xor_sync(0xffffffffu, s, off);
    float mean = s * (1.f/96.f);
    float d0 = v0-mean, d1 = v1-mean, d2 = v2-mean;
    float ss = d0*d0 + d1*d1 + d2*d2;
    #pragma unroll
    for (int off = 16; off; off >>= 1) ss += __shfl_xor_sync(0xffffffffu, ss, off);
    float rstd = rsqrtf(ss * (1.f/96.f) + 1e-5f);
    xn[row + lane]      = d0*rstd*gamma[lane]    + beta[lane];
    xn[row + 32 + lane] = d1*rstd*gamma[32+lane] + beta[32+lane];
    xn[row + 64 + lane] = d2*rstd*gamma[64+lane] + beta[64+lane];
}

// ---------------- bias+mask matrix precompute ----------------
// g_bm[head*8+cls][qi][j] = rel_bias + (region(qi)!=region(j) ? -100 : 0)
__global__ __launch_bounds__(128) void bias_prep(
    const float* __restrict__ relb, float* __restrict__ BM)
{
    int qi = blockIdx.x;            // 0..342
    int hc = blockIdx.y;            // 0..23
    int head = hc >> 3, cls = hc & 7;
    int di = qi/49, rr = qi%49, hi = rr/7, wi = rr%7;
    int ri = ((cls&4) ? ((di<4)?1:2)*9 : 0)
           + ((cls&2) ? ((hi<4)?1:2)*3 : 0)
           + ((cls&1) ? ((wi<4)?1:2)   : 0);
    float* row = BM + ((size_t)hc*NTOK + qi)*NTOK;
    for (int j = threadIdx.x; j < NTOK; j += 128) {
        int dj = j/49, r2 = j%49, hj = r2/7, wj = r2%7;
        int bidx = (di-dj+6)*169 + (hi-hj+6)*13 + (wi-wj+6);
        float b = relb[bidx*NHEAD + head];
        int rj = ((cls&4) ? ((dj<4)?1:2)*9 : 0)
               + ((cls&2) ? ((hj<4)?1:2)*3 : 0)
               + ((cls&1) ? ((wj<4)?1:2)   : 0);
        if (ri != rj) b -= 100.f;
        row[j] = b;
    }
}

// ---------------- HMMA GEMM (fp16 single-pass): Y = epi(X @ W^T + b) ----------------
#define LDB 104
#define A_OFF 0
#define B_OFF 26624
#define TC_SMEM 51200   // max(A+B = 46592, Dsm 128*100*4 = 51200)

#define EPI_STORE 0
#define EPI_PROJ  1
#define EPI_GELU  2
#define EPI_RES   3

template<int EPI>
__global__ __launch_bounds__(256) void tc_gemm(
    const float* __restrict__ X, const float* __restrict__ W,
    const float* __restrict__ bias, float* __restrict__ Y,
    float* __restrict__ xres, int Kdim, int O, int shifted)
{
    extern __shared__ char smem[];
    uint32_t sb = smem_u32(smem);
    int tid = threadIdx.x, wid = tid >> 5, lane = tid & 31;
    int m0 = blockIdx.x * 128, o0 = blockIdx.y * 96;
    int wm = (wid & 3) * 32, wn = (wid >> 2) * 48;

    float acc[2][6][4];
    #pragma unroll
    for (int i = 0; i < 2; i++)
        #pragma unroll
        for (int j = 0; j < 6; j++)
            #pragma unroll
            for (int t = 0; t < 4; t++) acc[i][j][t] = 0.f;

    int nch = Kdim / 96;
    for (int ch = 0; ch < nch; ch++) {
        int kc = ch * 96;
        if (ch) __syncthreads();
        #pragma unroll
        for (int i = 0; i < 12; i++) {
            int e = tid + i*256;
            int m = e / 24, k = (e % 24) * 4;
            float4 v = *(const float4*)(X + (size_t)(m0 + m)*Kdim + kc + k);
            *(uint2*)(smem + A_OFF + (uint32_t)(m*LDB + k)*2) =
                make_uint2(packh2(v.x, v.y), packh2(v.z, v.w));
        }
        #pragma unroll
        for (int i = 0; i < 9; i++) {
            int e = tid + i*256;
            int r = e / 24, k = (e % 24) * 4;
            float4 v = *(const float4*)(W + (size_t)(o0 + r)*Kdim + kc + k);
            *(uint2*)(smem + B_OFF + (uint32_t)(r*LDB + k)*2) =
                make_uint2(packh2(v.x, v.y), packh2(v.z, v.w));
        }
        __syncthreads();

        #pragma unroll
        for (int ks = 0; ks < 6; ks++) {
            int k = ks * 16;
            uint32_t af[2][4];
            #pragma unroll
            for (int mf = 0; mf < 2; mf++) {
                int r = wm + mf*16 + (lane & 15);
                int c = k + ((lane >> 4) << 3);
                ldsm4(af[mf], sb + A_OFF + (uint32_t)(r*LDB + c)*2);
            }
            uint32_t bf[6][2];
            #pragma unroll
            for (int nq = 0; nq < 3; nq++) {
                int r = wn + nq*16 + (lane & 7) + ((lane >> 4) << 3);
                int c = k + (((lane >> 3) & 1) << 3);
                uint32_t t4[4];
                ldsm4(t4, sb + B_OFF + (uint32_t)(r*LDB + c)*2);
                bf[nq*2][0] = t4[0];  bf[nq*2][1] = t4[1];
                bf[nq*2+1][0] = t4[2]; bf[nq*2+1][1] = t4[3];
            }
            #pragma unroll
            for (int mf = 0; mf < 2; mf++)
                #pragma unroll
                for (int nf = 0; nf < 6; nf++)
                    mma_fp16(acc[mf][nf], af[mf], bf[nf]);
        }
    }
    __syncthreads();

    float* Dsm = (float*)smem;
    #pragma unroll
    for (int mf = 0; mf < 2; mf++) {
        int row = wm + mf*16 + (lane >> 2);
        #pragma unroll
        for (int nf = 0; nf < 6; nf++) {
            int col = wn + nf*8 + (lane & 3)*2;
            float b0 = bias[o0 + col], b1 = bias[o0 + col + 1];
            Dsm[row*100 + col]       = acc[mf][nf][0] + b0;
            Dsm[row*100 + col + 1]   = acc[mf][nf][1] + b1;
            Dsm[(row+8)*100 + col]   = acc[mf][nf][2] + b0;
            Dsm[(row+8)*100 + col+1] = acc[mf][nf][3] + b1;
        }
    }
    __syncthreads();
    #pragma unroll
    for (int i = 0; i < 12; i++) {
        int e = tid + i*256;
        int m = e / 24, c = (e % 24) * 4;
        float4 v = *(const float4*)(Dsm + m*100 + c);
        int gm = m0 + m, o = o0 + c;
        if (EPI == EPI_STORE) {
            *(float4*)(Y + (size_t)gm*O + o) = v;
        } else if (EPI == EPI_GELU) {
            v.x = 0.5f*v.x*(1.f + erff(v.x*0.70710678118654752f));
            v.y = 0.5f*v.y*(1.f + erff(v.y*0.70710678118654752f));
            v.z = 0.5f*v.z*(1.f + erff(v.z*0.70710678118654752f));
            v.w = 0.5f*v.w*(1.f + erff(v.w*0.70710678118654752f));
            *(float4*)(Y + (size_t)gm*O + o) = v;
        } else if (EPI == EPI_RES) {
            float4 r = *(const float4*)(xres + (size_t)gm*CDIM + o);
            r.x += v.x; r.y += v.y; r.z += v.z; r.w += v.w;
            *(float4*)(xres + (size_t)gm*CDIM + o) = r;
        } else { // EPI_PROJ
            int win = gm / NTOK, n = gm % NTOK;
            int b = win >> 6, wrem = win & 63;
            int bd = wrem >> 4, bh = (wrem >> 2) & 3, bw = wrem & 3;
            int ld = n / 49, rr2 = n % 49, lh = rr2 / 7, lw = rr2 % 7;
            int d = bd*7 + ld, h = bh*7 + lh, w = bw*7 + lw;
            if (shifted) {
                d += 3; if (d >= GRD) d -= GRD;
                h += 3; if (h >= GRD) h -= GRD;
                w += 3; if (w >= GRD) w -= GRD;
            }
            size_t drow = (size_t)(((b*GRD + d)*GRD + h)*GRD + w) * CDIM;
            float4 r = *(const float4*)(xres + drow + o);
            r.x += v.x; r.y += v.y; r.z += v.z; r.w += v.w;
            *(float4*)(xres + drow + o) = r;
        }
    }
}

// ---------------- HMMA flash attention ----------------
// grid (BN*NHEAD, 3 q-tiles), 128 threads (4 warps, warp = 32 q rows).
// K tiles of 64 keys; S = Q K^T and O += P V via mma fp16.
#define QLD 40    // Qs/Ks row stride in halves
#define VLD 72    // Vt row stride in halves

__global__ __launch_bounds__(128) void attn_mma_kernel(
    const float* __restrict__ qkv, float* __restrict__ aout,
    const float* __restrict__ BM, int shifted)
{
    __shared__ half Qs[128*QLD];
    __shared__ half Ksm[64*QLD];
    __shared__ half Vt[32*VLD];
    uint32_t sQ = smem_u32(Qs), sK = smem_u32(Ksm), sV = smem_u32(Vt);

    int tid = threadIdx.x, wid = tid >> 5, lane = tid & 31;
    int bx = blockIdx.x;
    int win = bx / NHEAD, head = bx % NHEAD;
    int base = win * NTOK;
    int q0 = blockIdx.y * 128;
    int wrem = win & 63;
    int bd = wrem >> 4, bh = (wrem >> 2) & 3, bw = wrem & 3;
    int cls = shifted ? (((bd==3)<<2) | ((bh==3)<<1) | (bw==3)) : 0;
    const float* bmb = BM + (size_t)(head*8 + cls)*NTOK*NTOK;

    // ---- stage Q (scaled, fp16) ----
    {
        int r = tid, qi = q0 + r;
        half2* dst = (half2*)(Qs + r*QLD);
        if (qi < NTOK) {
            const float4* src = (const float4*)(qkv + (size_t)(base+qi)*QKVO + head*HDIM);
            #pragma unroll
            for (int t = 0; t < 8; t++) {
                float4 v = src[t];
                dst[2*t]   = __floats2half2_rn(v.x*SCALE, v.y*SCALE);
                dst[2*t+1] = __floats2half2_rn(v.z*SCALE, v.w*SCALE);
            }
        } else {
            #pragma unroll
            for (int t = 0; t < 16; t++) dst[t] = __floats2half2_rn(0.f, 0.f);
        }
    }
    __syncthreads();

    // ---- Q fragments ----
    int wm = wid * 32;
    uint32_t af[2][2][4];
    #pragma unroll
    for (int mf = 0; mf < 2; mf++)
        #pragma unroll
        for (int ks = 0; ks < 2; ks++) {
            int r = wm + mf*16 + (lane & 15);
            int c = ks*16 + ((lane >> 4) << 3);
            ldsm4(af[mf][ks], sQ + (uint32_t)(r*QLD + c)*2);
        }

    float o[2][4][4];
    #pragma unroll
    for (int mf = 0; mf < 2; mf++)
        #pragma unroll
        for (int n = 0; n < 4; n++)
            #pragma unroll
            for (int t = 0; t < 4; t++) o[mf][n][t] = 0.f;
    float mrun[2][2] = {{-1e30f,-1e30f},{-1e30f,-1e30f}};
    float lrun[2][2] = {{0.f,0.f},{0.f,0.f}};

    int lq = lane >> 2, lc = (lane & 3) * 2;

    for (int kt = 0; kt < 6; kt++) {
        if (kt) __syncthreads();
        // ---- stage K tile + V^T tile ----
        {
            int r = tid >> 1, cg = (tid & 1) * 16;
            int key = kt*64 + r;
            half2* kd = (half2*)(Ksm + r*QLD + cg);
            if (key < NTOK) {
                const float* rowp = qkv + (size_t)(base+key)*QKVO + head*HDIM;
                const float4* ksrc = (const float4*)(rowp + CDIM + cg);
                #pragma unroll
                for (int t = 0; t < 4; t++) {
                    float4 v = ksrc[t];
                    kd[2*t]   = __floats2half2_rn(v.x, v.y);
                    kd[2*t+1] = __floats2half2_rn(v.z, v.w);
                }
                const float4* vsrc = (const float4*)(rowp + 2*CDIM + cg);
                #pragma unroll
                for (int t = 0; t < 4; t++) {
                    float4 v = vsrc[t];
                    Vt[(cg + 4*t    )*VLD + r] = __float2half(v.x);
                    Vt[(cg + 4*t + 1)*VLD + r] = __float2half(v.y);
                    Vt[(cg + 4*t + 2)*VLD + r] = __float2half(v.z);
                    Vt[(cg + 4*t + 3)*VLD + r] = __float2half(v.w);
                }
            } else {
                #pragma unroll
                for (int t = 0; t < 8; t++) kd[t] = __floats2half2_rn(0.f, 0.f);
                #pragma unroll
                for (int t = 0; t < 16; t++) Vt[(cg + t)*VLD + r] = __float2half(0.f);
            }
        }
        __syncthreads();

        // ---- S = Q K^T ----
        float sf[2][8][4];
        #pragma unroll
        for (int mf = 0; mf < 2; mf++)
            #pragma unroll
            for (int nf = 0; nf < 8; nf++)
                #pragma unroll
                for (int t = 0; t < 4; t++) sf[mf][nf][t] = 0.f;
        #pragma unroll
        for (int ks = 0; ks < 2; ks++) {
            uint32_t bf[8][2];
            #pragma unroll
            for (int nq = 0; nq < 4; nq++) {
                int r = nq*16 + (lane & 7) + ((lane >> 4) << 3);
                int c = ks*16 + (((lane >> 3) & 1) << 3);
                uint32_t t4[4];
                ldsm4(t4, sK + (uint32_t)(r*QLD + c)*2);
                bf[nq*2][0] = t4[0];  bf[nq*2][1] = t4[1];
                bf[nq*2+1][0] = t4[2]; bf[nq*2+1][1] = t4[3];
            }
            #pragma unroll
            for (int mf = 0; mf < 2; mf++)
                #pragma unroll
                for (int nf = 0; nf < 8; nf++)
                    mma_fp16(sf[mf][nf], af[mf][ks], bf[nf]);
        }

        // ---- bias + mask + online softmax ----
        #pragma unroll
        for (int mf = 0; mf < 2; mf++) {
            #pragma unroll
            for (int h = 0; h < 2; h++) {
                int qi = q0 + wm + mf*16 + h*8 + lq;
                bool qv = qi < NTOK;
                const float* bmrow = bmb + (size_t)(qv ? qi : 0)*NTOK;
                float vmax = -1e30f;
                #pragma unroll
                for (int nf = 0; nf < 8; nf++) {
                    #pragma unroll
                    for (int u = 0; u < 2; u++) {
                        int j = kt*64 + nf*8 + lc + u;
                        float s = sf[mf][nf][h*2+u];
                        s = (qv && j < NTOK) ? s + bmrow[j] : -1e30f;
                        sf[mf][nf][h*2+u] = s;
                        vmax = fmaxf(vmax, s);
                    }
                }
                vmax = fmaxf(vmax, __shfl_xor_sync(0xffffffffu, vmax, 1));
                vmax = fmaxf(vmax, __shfl_xor_sync(0xffffffffu, vmax, 2));
                float mnew = fmaxf(mrun[mf][h], vmax);
                float al = __expf(mrun[mf][h] - mnew);
                mrun[mf][h] = mnew;
                float ls = 0.f;
                #pragma unroll
                for (int nf = 0; nf < 8; nf++) {
                    #pragma unroll
                    for (int u = 0; u < 2; u++) {
                        float p = __expf(sf[mf][nf][h*2+u] - mnew);
                        sf[mf][nf][h*2+u] = p;
                        ls += p;
                    }
                }
                lrun[mf][h] = lrun[mf][h]*al + ls;
                #pragma unroll
                for (int n = 0; n < 4; n++) {
                    o[mf][n][h*2]   *= al;
                    o[mf][n][h*2+1] *= al;
                }
            }
        }

        // ---- O += P V ----
        #pragma unroll
        for (int ks4 = 0; ks4 < 4; ks4++) {
            uint32_t bv[4][2];
            #pragma unroll
            for (int nq = 0; nq < 2; nq++) {
                int r = nq*16 + (lane & 7) + ((lane >> 4) << 3);
                int c = ks4*16 + (((lane >> 3) & 1) << 3);
                uint32_t t4[4];
                ldsm4(t4, sV + (uint32_t)(r*VLD + c)*2);
                bv[nq*2][0] = t4[0];  bv[nq*2][1] = t4[1];
                bv[nq*2+1][0] = t4[2]; bv[nq*2+1][1] = t4[3];
            }
            #pragma unroll
            for (int mf = 0; mf < 2; mf++) {
                uint32_t pa[4];
                pa[0] = packh2(sf[mf][2*ks4][0],   sf[mf][2*ks4][1]);
                pa[1] = packh2(sf[mf][2*ks4][2],   sf[mf][2*ks4][3]);
                pa[2] = packh2(sf[mf][2*ks4+1][0], sf[mf][2*ks4+1][1]);
                pa[3] = packh2(sf[mf][2*ks4+1][2], sf[mf][2*ks4+1][3]);
                #pragma unroll
                for (int n = 0; n < 4; n++)
                    mma_fp16(o[mf][n], pa, bv[n]);
            }
        }
    }

    // ---- finalize: 1/l and store ----
    #pragma unroll
    for (int mf = 0; mf < 2; mf++) {
        #pragma unroll
        for (int h = 0; h < 2; h++) {
            float l = lrun[mf][h];
            l += __shfl_xor_sync(0xffffffffu, l, 1);
            l += __shfl_xor_sync(0xffffffffu, l, 2);
            float inv = 1.f / l;
            int qi = q0 + wm + mf*16 + h*8 + lq;
            if (qi < NTOK) {
                float* orow = aout + (size_t)(base+qi)*CDIM + head*HDIM;
                #pragma unroll
                for (int n = 0; n < 4; n++) {
                    float2 v;
                    v.x = o[mf][n][h*2]   * inv;
                    v.y = o[mf][n][h*2+1] * inv;
                    *(float2*)(orow + n*8 + lc) = v;
                }
            }
        }
    }
}

// ---------------- launch ----------------
extern "C" void kernel_launch(void* const* d_in, const int* in_sizes, int n_in,
                              void* d_out, int out_size)
{
    const float* x_in   = (const float*)d_in[0];
    const float* n1g    = (const float*)d_in[1];
    const float* n1b    = (const float*)d_in[2];
    const float* qkvw   = (const float*)d_in[3];
    const float* qkvb   = (const float*)d_in[4];
    const float* relb   = (const float*)d_in[5];
    const float* projw  = (const float*)d_in[6];
    const float* projb  = (const float*)d_in[7];
    const float* n2g    = (const float*)d_in[8];
    const float* n2b    = (const float*)d_in[9];
    const float* fc1w   = (const float*)d_in[10];
    const float* fc1b   = (const float*)d_in[11];
    const float* fc2w   = (const float*)d_in[12];
    const float* fc2b   = (const float*)d_in[13];
    float* out = (float*)d_out;

    float *px, *pxw, *pqkv, *paout, *pxn, *ph1, *pbm;
    cudaGetSymbolAddress((void**)&px,    g_x);
    cudaGetSymbolAddress((void**)&pxw,   g_xw);
    cudaGetSymbolAddress((void**)&pqkv,  g_qkv);
    cudaGetSymbolAddress((void**)&paout, g_aout);
    cudaGetSymbolAddress((void**)&pxn,   g_xn);
    cudaGetSymbolAddress((void**)&ph1,   g_h1);
    cudaGetSymbolAddress((void**)&pbm,   g_bm);

    cudaFuncSetAttribute(tc_gemm<EPI_STORE>, cudaFuncAttributeMaxDynamicSharedMemorySize, TC_SMEM);
    cudaFuncSetAttribute(tc_gemm<EPI_PROJ>,  cudaFuncAttributeMaxDynamicSharedMemorySize, TC_SMEM);
    cudaFuncSetAttribute(tc_gemm<EPI_GELU>,  cudaFuncAttributeMaxDynamicSharedMemorySize, TC_SMEM);
    cudaFuncSetAttribute(tc_gemm<EPI_RES>,   cudaFuncAttributeMaxDynamicSharedMemorySize, TC_SMEM);

    int n4 = TOK*CDIM/4;
    copyk<<<1024, 256>>>((const float4*)x_in, (float4*)px, n4);

    const int MB = TOK/128;   // 343 exact
    for (int L = 0; L < 2; L++) {
        int shifted = L & 1;
        bias_prep<<<dim3(NTOK, 24), 128>>>(relb + (size_t)L*NBIAS*NHEAD, pbm);
        ln_part_kernel<<<TOK/4, 128>>>(px, pxw, n1g + L*CDIM, n1b + L*CDIM, shifted);
        tc_gemm<EPI_STORE><<<dim3(MB, QKVO/96), 256, TC_SMEM>>>(
            pxw, qkvw + (size_t)L*QKVO*CDIM, qkvb + L*QKVO, pqkv, nullptr, CDIM, QKVO, 0);
        attn_mma_kernel<<<dim3(BN*NHEAD, 3), 128>>>(pqkv, paout, pbm, shifted);
        tc_gemm<EPI_PROJ><<<dim3(MB, 1), 256, TC_SMEM>>>(
            paout, projw + (size_t)L*CDIM*CDIM, projb + L*CDIM, nullptr, px, CDIM, CDIM, shifted);
        ln2_kernel<<<TOK/4, 128>>>(px, pxn, n2g + L*CDIM, n2b + L*CDIM);
        tc_gemm<EPI_GELU><<<dim3(MB, FF/96), 256, TC_SMEM>>>(
            pxn, fc1w + (size_t)L*FF*CDIM, fc1b + L*FF, ph1, nullptr, CDIM, FF, 0);
        tc_gemm<EPI_RES><<<dim3(MB, 1), 256, TC_SMEM>>>(
            ph1, fc2w + (size_t)L*CDIM*FF, fc2b + L*CDIM, nullptr, px, FF, CDIM, 0);
    }

    copyk<<<1024, 256>>>((const float4*)px, (float4*)out, n4);
}

// round 12
// speedup vs baseline: 5.1947x; 1.4838x over previous
#include <cuda_runtime.h>
#include <cuda_fp16.h>
#include <math.h>
#include <stdint.h>

// ---------------- problem constants ----------------
#define BATCH 2
#define GRD 28
#define CDIM 96
#define NHEAD 3
#define HDIM 32
#define NTOK 343
#define NWIN 64
#define BN (BATCH*NWIN)
#define TOK (BATCH*GRD*GRD*GRD)   // 43904
#define QKVO (3*CDIM)   // 288
#define FF (4*CDIM)     // 384
#define NBIAS 2197
#define SCALE 0.17677669529663687f

// ---------------- scratch buffers ----------------
__device__ float g_x   [TOK*CDIM];
__device__ float g_xw  [TOK*CDIM];
__device__ float g_qkv [TOK*QKVO];
__device__ float g_aout[TOK*CDIM];
__device__ float g_xn  [TOK*CDIM];
__device__ float g_h1  [TOK*FF];
__device__ float g_bm  [24*NTOK*NTOK + 16];

// ---------------- helpers ----------------
__device__ __forceinline__ uint32_t smem_u32(const void* p) {
    uint32_t a;
    asm("{ .reg .u64 t; cvta.to.shared.u64 t, %1; cvt.u32.u64 %0, t; }" : "=r"(a) : "l"(p));
    return a;
}
__device__ __forceinline__ void ldsm4(uint32_t* r, uint32_t addr) {
    asm volatile("ldmatrix.sync.aligned.m8n8.x4.shared.b16 {%0,%1,%2,%3}, [%4];"
        : "=r"(r[0]), "=r"(r[1]), "=r"(r[2]), "=r"(r[3]) : "r"(addr));
}
__device__ __forceinline__ void mma_fp16(float* c, const uint32_t* a, const uint32_t* b) {
    asm volatile("mma.sync.aligned.m16n8k16.row.col.f32.f16.f16.f32 "
        "{%0,%1,%2,%3}, {%4,%5,%6,%7}, {%8,%9}, {%0,%1,%2,%3};"
        : "+f"(c[0]), "+f"(c[1]), "+f"(c[2]), "+f"(c[3])
        : "r"(a[0]), "r"(a[1]), "r"(a[2]), "r"(a[3]), "r"(b[0]), "r"(b[1]));
}
__device__ __forceinline__ uint32_t packh2(float a, float b) {
    half2 h = __floats2half2_rn(a, b);
    return *(uint32_t*)&h;
}

// ---------------- copy ----------------
__global__ void copyk(const float4* __restrict__ s, float4* __restrict__ d, int n) {
    for (int i = blockIdx.x*blockDim.x + threadIdx.x; i < n; i += gridDim.x*blockDim.x)
        d[i] = s[i];
}

// ---------------- LN1 + shift + window partition ----------------
__global__ __launch_bounds__(128) void ln_part_kernel(
    const float* __restrict__ x, float* __restrict__ xw,
    const float* __restrict__ gamma, const float* __restrict__ beta, int shifted)
{
    int warp = threadIdx.x >> 5, lane = threadIdx.x & 31;
    int g = blockIdx.x*4 + warp;
    int win = g / NTOK, n = g % NTOK;
    int b = win >> 6, wrem = win & 63;
    int bd = wrem >> 4, bh = (wrem >> 2) & 3, bw = wrem & 3;
    int ld = n / 49, rr = n % 49, lh = rr / 7, lw = rr % 7;
    int d = bd*7 + ld, h = bh*7 + lh, w = bw*7 + lw;
    if (shifted) {
        d += 3; if (d >= GRD) d -= GRD;
        h += 3; if (h >= GRD) h -= GRD;
        w += 3; if (w >= GRD) w -= GRD;
    }
    size_t row = (size_t)(((b*GRD + d)*GRD + h)*GRD + w) * CDIM;
    float v0 = x[row + lane], v1 = x[row + 32 + lane], v2 = x[row + 64 + lane];
    float s = v0 + v1 + v2;
    #pragma unroll
    for (int off = 16; off; off >>= 1) s += __shfl_xor_sync(0xffffffffu, s, off);
    float mean = s * (1.f/96.f);
    float d0 = v0-mean, d1 = v1-mean, d2 = v2-mean;
    float ss = d0*d0 + d1*d1 + d2*d2;
    #pragma unroll
    for (int off = 16; off; off >>= 1) ss += __shfl_xor_sync(0xffffffffu, ss, off);
    float rstd = rsqrtf(ss * (1.f/96.f) + 1e-5f);
    size_t orow = (size_t)g * CDIM;
    xw[orow + lane]      = d0*rstd*gamma[lane]    + beta[lane];
    xw[orow + 32 + lane] = d1*rstd*gamma[32+lane] + beta[32+lane];
    xw[orow + 64 + lane] = d2*rstd*gamma[64+lane] + beta[64+lane];
}

// ---------------- bias+mask matrix precompute ----------------
__global__ __launch_bounds__(128) void bias_prep(
    const float* __restrict__ relb, float* __restrict__ BM)
{
    int qi = blockIdx.x;
    int hc = blockIdx.y;
    int head = hc >> 3, cls = hc & 7;
    int di = qi/49, rr = qi%49, hi = rr/7, wi = rr%7;
    int ri = ((cls&4) ? ((di<4)?1:2)*9 : 0)
           + ((cls&2) ? ((hi<4)?1:2)*3 : 0)
           + ((cls&1) ? ((wi<4)?1:2)   : 0);
    float* row = BM + ((size_t)hc*NTOK + qi)*NTOK;
    for (int j = threadIdx.x; j < NTOK; j += 128) {
        int dj = j/49, r2 = j%49, hj = r2/7, wj = r2%7;
        int bidx = (di-dj+6)*169 + (hi-hj+6)*13 + (wi-wj+6);
        float b = relb[bidx*NHEAD + head];
        int rj = ((cls&4) ? ((dj<4)?1:2)*9 : 0)
               + ((cls&2) ? ((hj<4)?1:2)*3 : 0)
               + ((cls&1) ? ((wj<4)?1:2)   : 0);
        if (ri != rj) b -= 100.f;
        row[j] = b;
    }
}

// ---------------- HMMA GEMM (fp16): Y = epi(X @ W^T + b) ----------------
#define LDB 104
#define A_OFF 0
#define B_OFF 26624
#define TC_SMEM 51200

#define EPI_STORE  0
#define EPI_PROJLN 1   // proj + window-reverse + residual + fused LN2
#define EPI_GELU   2
#define EPI_RES    3   // residual add (+ optional copy to Yout)

template<int EPI>
__global__ __launch_bounds__(256, 2) void tc_gemm(
    const float* __restrict__ X, const float* __restrict__ W,
    const float* __restrict__ bias, float* __restrict__ Y,
    float* __restrict__ xres, int Kdim, int O, int shifted,
    const float* __restrict__ g2, const float* __restrict__ b2,
    float* __restrict__ xn_out)
{
    extern __shared__ char smem[];
    uint32_t sb = smem_u32(smem);
    int tid = threadIdx.x, wid = tid >> 5, lane = tid & 31;
    int m0 = blockIdx.x * 128, o0 = blockIdx.y * 96;
    int wm = (wid & 3) * 32, wn = (wid >> 2) * 48;

    float acc[2][6][4];
    #pragma unroll
    for (int i = 0; i < 2; i++)
        #pragma unroll
        for (int j = 0; j < 6; j++)
            #pragma unroll
            for (int t = 0; t < 4; t++) acc[i][j][t] = 0.f;

    int nch = Kdim / 96;
    for (int ch = 0; ch < nch; ch++) {
        int kc = ch * 96;
        if (ch) __syncthreads();
        #pragma unroll
        for (int i = 0; i < 12; i++) {
            int e = tid + i*256;
            int m = e / 24, k = (e % 24) * 4;
            float4 v = *(const float4*)(X + (size_t)(m0 + m)*Kdim + kc + k);
            *(uint2*)(smem + A_OFF + (uint32_t)(m*LDB + k)*2) =
                make_uint2(packh2(v.x, v.y), packh2(v.z, v.w));
        }
        #pragma unroll
        for (int i = 0; i < 9; i++) {
            int e = tid + i*256;
            int r = e / 24, k = (e % 24) * 4;
            float4 v = *(const float4*)(W + (size_t)(o0 + r)*Kdim + kc + k);
            *(uint2*)(smem + B_OFF + (uint32_t)(r*LDB + k)*2) =
                make_uint2(packh2(v.x, v.y), packh2(v.z, v.w));
        }
        __syncthreads();

        #pragma unroll
        for (int ks = 0; ks < 6; ks++) {
            int k = ks * 16;
            uint32_t af[2][4];
            #pragma unroll
            for (int mf = 0; mf < 2; mf++) {
                int r = wm + mf*16 + (lane & 15);
                int c = k + ((lane >> 4) << 3);
                ldsm4(af[mf], sb + A_OFF + (uint32_t)(r*LDB + c)*2);
            }
            uint32_t bf[6][2];
            #pragma unroll
            for (int nq = 0; nq < 3; nq++) {
                int r = wn + nq*16 + (lane & 7) + ((lane >> 4) << 3);
                int c = k + (((lane >> 3) & 1) << 3);
                uint32_t t4[4];
                ldsm4(t4, sb + B_OFF + (uint32_t)(r*LDB + c)*2);
                bf[nq*2][0] = t4[0];  bf[nq*2][1] = t4[1];
                bf[nq*2+1][0] = t4[2]; bf[nq*2+1][1] = t4[3];
            }
            #pragma unroll
            for (int mf = 0; mf < 2; mf++)
                #pragma unroll
                for (int nf = 0; nf < 6; nf++)
                    mma_fp16(acc[mf][nf], af[mf], bf[nf]);
        }
    }
    __syncthreads();

    float* Dsm = (float*)smem;
    #pragma unroll
    for (int mf = 0; mf < 2; mf++) {
        int row = wm + mf*16 + (lane >> 2);
        #pragma unroll
        for (int nf = 0; nf < 6; nf++) {
            int col = wn + nf*8 + (lane & 3)*2;
            float b0 = bias[o0 + col], b1 = bias[o0 + col + 1];
            Dsm[row*100 + col]       = acc[mf][nf][0] + b0;
            Dsm[row*100 + col + 1]   = acc[mf][nf][1] + b1;
            Dsm[(row+8)*100 + col]   = acc[mf][nf][2] + b0;
            Dsm[(row+8)*100 + col+1] = acc[mf][nf][3] + b1;
        }
    }
    __syncthreads();

    if (EPI == EPI_PROJLN) {
        // 2 threads per row; residual add + LN2, writes xres (px) and xn_out
        int row = tid >> 1, half = tid & 1, c0 = half * 48;
        int gm = m0 + row;
        int win = gm / NTOK, n = gm % NTOK;
        int b = win >> 6, wrem = win & 63;
        int bd = wrem >> 4, bh = (wrem >> 2) & 3, bw = wrem & 3;
        int ld = n / 49, rr2 = n % 49, lh = rr2 / 7, lw = rr2 % 7;
        int d = bd*7 + ld, h = bh*7 + lh, w = bw*7 + lw;
        if (shifted) {
            d += 3; if (d >= GRD) d -= GRD;
            h += 3; if (h >= GRD) h -= GRD;
            w += 3; if (w >= GRD) w -= GRD;
        }
        size_t drow = (size_t)(((b*GRD + d)*GRD + h)*GRD + w) * CDIM;
        float* dst = xres + drow;
        float s = 0.f, ss = 0.f;
        #pragma unroll
        for (int i = 0; i < 12; i++) {
            int c = c0 + i*4;
            float4 v = *(const float4*)(Dsm + row*100 + c);
            float4 r = *(const float4*)(dst + c);
            r.x += v.x; r.y += v.y; r.z += v.z; r.w += v.w;
            *(float4*)(Dsm + row*100 + c) = r;
            *(float4*)(dst + c) = r;
            s  += r.x + r.y + r.z + r.w;
            ss += r.x*r.x + r.y*r.y + r.z*r.z + r.w*r.w;
        }
        s  += __shfl_xor_sync(0xffffffffu, s, 1);
        ss += __shfl_xor_sync(0xffffffffu, ss, 1);
        float mean = s * (1.f/96.f);
        float var  = ss * (1.f/96.f) - mean*mean;
        float rstd = rsqrtf(var + 1e-5f);
        float* nd = xn_out + drow;
        #pragma unroll
        for (int i = 0; i < 12; i++) {
            int c = c0 + i*4;
            float4 r = *(const float4*)(Dsm + row*100 + c);
            float4 y;
            y.x = (r.x - mean)*rstd*g2[c]   + b2[c];
            y.y = (r.y - mean)*rstd*g2[c+1] + b2[c+1];
            y.z = (r.z - mean)*rstd*g2[c+2] + b2[c+2];
            y.w = (r.w - mean)*rstd*g2[c+3] + b2[c+3];
            *(float4*)(nd + c) = y;
        }
    } else {
        #pragma unroll
        for (int i = 0; i < 12; i++) {
            int e = tid + i*256;
            int m = e / 24, c = (e % 24) * 4;
            float4 v = *(const float4*)(Dsm + m*100 + c);
            int gm = m0 + m, o = o0 + c;
            if (EPI == EPI_STORE) {
                *(float4*)(Y + (size_t)gm*O + o) = v;
            } else if (EPI == EPI_GELU) {
                v.x = 0.5f*v.x*(1.f + erff(v.x*0.70710678118654752f));
                v.y = 0.5f*v.y*(1.f + erff(v.y*0.70710678118654752f));
                v.z = 0.5f*v.z*(1.f + erff(v.z*0.70710678118654752f));
                v.w = 0.5f*v.w*(1.f + erff(v.w*0.70710678118654752f));
                *(float4*)(Y + (size_t)gm*O + o) = v;
            } else { // EPI_RES
                float4 r = *(const float4*)(xres + (size_t)gm*CDIM + o);
                r.x += v.x; r.y += v.y; r.z += v.z; r.w += v.w;
                *(float4*)(xres + (size_t)gm*CDIM + o) = r;
                if (Y) *(float4*)(Y + (size_t)gm*CDIM + o) = r;
            }
        }
    }
}

// ---------------- HMMA flash attention ----------------
#define QLD 40
#define VLD 72

__global__ __launch_bounds__(128) void attn_mma_kernel(
    const float* __restrict__ qkv, float* __restrict__ aout,
    const float* __restrict__ BM, int shifted)
{
    __shared__ half Qs[128*QLD];
    __shared__ half Ksm[64*QLD];
    __shared__ half Vt[32*VLD];
    uint32_t sQ = smem_u32(Qs), sK = smem_u32(Ksm), sV = smem_u32(Vt);

    int tid = threadIdx.x, wid = tid >> 5, lane = tid & 31;
    int bx = blockIdx.x;
    int win = bx / NHEAD, head = bx % NHEAD;
    int base = win * NTOK;
    int q0 = blockIdx.y * 128;
    int wrem = win & 63;
    int bd = wrem >> 4, bh = (wrem >> 2) & 3, bw = wrem & 3;
    int cls = shifted ? (((bd==3)<<2) | ((bh==3)<<1) | (bw==3)) : 0;
    const float* bmb = BM + (size_t)(head*8 + cls)*NTOK*NTOK;

    {
        int r = tid, qi = q0 + r;
        half2* dst = (half2*)(Qs + r*QLD);
        if (qi < NTOK) {
            const float4* src = (const float4*)(qkv + (size_t)(base+qi)*QKVO + head*HDIM);
            #pragma unroll
            for (int t = 0; t < 8; t++) {
                float4 v = src[t];
                dst[2*t]   = __floats2half2_rn(v.x*SCALE, v.y*SCALE);
                dst[2*t+1] = __floats2half2_rn(v.z*SCALE, v.w*SCALE);
            }
        } else {
            #pragma unroll
            for (int t = 0; t < 16; t++) dst[t] = __floats2half2_rn(0.f, 0.f);
        }
    }
    __syncthreads();

    int wm = wid * 32;
    uint32_t af[2][2][4];
    #pragma unroll
    for (int mf = 0; mf < 2; mf++)
        #pragma unroll
        for (int ks = 0; ks < 2; ks++) {
            int r = wm + mf*16 + (lane & 15);
            int c = ks*16 + ((lane >> 4) << 3);
            ldsm4(af[mf][ks], sQ + (uint32_t)(r*QLD + c)*2);
        }

    float o[2][4][4];
    #pragma unroll
    for (int mf = 0; mf < 2; mf++)
        #pragma unroll
        for (int n = 0; n < 4; n++)
            #pragma unroll
            for (int t = 0; t < 4; t++) o[mf][n][t] = 0.f;
    float mrun[2][2] = {{-1e30f,-1e30f},{-1e30f,-1e30f}};
    float lrun[2][2] = {{0.f,0.f},{0.f,0.f}};

    int lq = lane >> 2, lc = (lane & 3) * 2;

    for (int kt = 0; kt < 6; kt++) {
        if (kt) __syncthreads();
        {
            int r = tid >> 1, cg = (tid & 1) * 16;
            int key = kt*64 + r;
            half2* kd = (half2*)(Ksm + r*QLD + cg);
            if (key < NTOK) {
                const float* rowp = qkv + (size_t)(base+key)*QKVO + head*HDIM;
                const float4* ksrc = (const float4*)(rowp + CDIM + cg);
                #pragma unroll
                for (int t = 0; t < 4; t++) {
                    float4 v = ksrc[t];
                    kd[2*t]   = __floats2half2_rn(v.x, v.y);
                    kd[2*t+1] = __floats2half2_rn(v.z, v.w);
                }
                const float4* vsrc = (const float4*)(rowp + 2*CDIM + cg);
                #pragma unroll
                for (int t = 0; t < 4; t++) {
                    float4 v = vsrc[t];
                    Vt[(cg + 4*t    )*VLD + r] = __float2half(v.x);
                    Vt[(cg + 4*t + 1)*VLD + r] = __float2half(v.y);
                    Vt[(cg + 4*t + 2)*VLD + r] = __float2half(v.z);
                    Vt[(cg + 4*t + 3)*VLD + r] = __float2half(v.w);
                }
            } else {
                #pragma unroll
                for (int t = 0; t < 8; t++) kd[t] = __floats2half2_rn(0.f, 0.f);
                #pragma unroll
                for (int t = 0; t < 16; t++) Vt[(cg + t)*VLD + r] = __float2half(0.f);
            }
        }
        __syncthreads();

        float sf[2][8][4];
        #pragma unroll
        for (int mf = 0; mf < 2; mf++)
            #pragma unroll
            for (int nf = 0; nf < 8; nf++)
                #pragma unroll
                for (int t = 0; t < 4; t++) sf[mf][nf][t] = 0.f;
        #pragma unroll
        for (int ks = 0; ks < 2; ks++) {
            uint32_t bf[8][2];
            #pragma unroll
            for (int nq = 0; nq < 4; nq++) {
                int r = nq*16 + (lane & 7) + ((lane >> 4) << 3);
                int c = ks*16 + (((lane >> 3) & 1) << 3);
                uint32_t t4[4];
                ldsm4(t4, sK + (uint32_t)(r*QLD + c)*2);
                bf[nq*2][0] = t4[0];  bf[nq*2][1] = t4[1];
                bf[nq*2+1][0] = t4[2]; bf[nq*2+1][1] = t4[3];
            }
            #pragma unroll
            for (int mf = 0; mf < 2; mf++)
                #pragma unroll
                for (int nf = 0; nf < 8; nf++)
                    mma_fp16(sf[mf][nf], af[mf][ks], bf[nf]);
        }

        #pragma unroll
        for (int mf = 0; mf < 2; mf++) {
            #pragma unroll
            for (int h = 0; h < 2; h++) {
                int qi = q0 + wm + mf*16 + h*8 + lq;
                bool qv = qi < NTOK;
                const float* bmrow = bmb + (size_t)(qv ? qi : 0)*NTOK;
                float vmax = -1e30f;
                #pragma unroll
                for (int nf = 0; nf < 8; nf++) {
                    #pragma unroll
                    for (int u = 0; u < 2; u++) {
                        int j = kt*64 + nf*8 + lc + u;
                        float s = sf[mf][nf][h*2+u];
                        s = (qv && j < NTOK) ? s + bmrow[j] : -1e30f;
                        sf[mf][nf][h*2+u] = s;
                        vmax = fmaxf(vmax, s);
                    }
                }
                vmax = fmaxf(vmax, __shfl_xor_sync(0xffffffffu, vmax, 1));
                vmax = fmaxf(vmax, __shfl_xor_sync(0xffffffffu, vmax, 2));
                float mnew = fmaxf(mrun[mf][h], vmax);
                float al = __expf(mrun[mf][h] - mnew);
                mrun[mf][h] = mnew;
                float ls = 0.f;
                #pragma unroll
                for (int nf = 0; nf < 8; nf++) {
                    #pragma unroll
                    for (int u = 0; u < 2; u++) {
                        float p = __expf(sf[mf][nf][h*2+u] - mnew);
                        sf[mf][nf][h*2+u] = p;
                        ls += p;
                    }
                }
                lrun[mf][h] = lrun[mf][h]*al + ls;
                #pragma unroll
                for (int n = 0; n < 4; n++) {
                    o[mf][n][h*2]   *= al;
                    o[mf][n][h*2+1] *= al;
                }
            }
        }

        #pragma unroll
        for (int ks4 = 0; ks4 < 4; ks4++) {
            uint32_t bv[4][2];
            #pragma unroll
            for (int nq = 0; nq < 2; nq++) {
                int r = nq*16 + (lane & 7) + ((lane >> 4) << 3);
                int c = ks4*16 + (((lane >> 3) & 1) << 3);
                uint32_t t4[4];
                ldsm4(t4, sV + (uint32_t)(r*VLD + c)*2);
                bv[nq*2][0] = t4[0];  bv[nq*2][1] = t4[1];
                bv[nq*2+1][0] = t4[2]; bv[nq*2+1][1] = t4[3];
            }
            #pragma unroll
            for (int mf = 0; mf < 2; mf++) {
                uint32_t pa[4];
                pa[0] = packh2(sf[mf][2*ks4][0],   sf[mf][2*ks4][1]);
                pa[1] = packh2(sf[mf][2*ks4][2],   sf[mf][2*ks4][3]);
                pa[2] = packh2(sf[mf][2*ks4+1][0], sf[mf][2*ks4+1][1]);
                pa[3] = packh2(sf[mf][2*ks4+1][2], sf[mf][2*ks4+1][3]);
                #pragma unroll
                for (int n = 0; n < 4; n++)
                    mma_fp16(o[mf][n], pa, bv[n]);
            }
        }
    }

    #pragma unroll
    for (int mf = 0; mf < 2; mf++) {
        #pragma unroll
        for (int h = 0; h < 2; h++) {
            float l = lrun[mf][h];
            l += __shfl_xor_sync(0xffffffffu, l, 1);
            l += __shfl_xor_sync(0xffffffffu, l, 2);
            float inv = 1.f / l;
            int qi = q0 + wm + mf*16 + h*8 + lq;
            if (qi < NTOK) {
                float* orow = aout + (size_t)(base+qi)*CDIM + head*HDIM;
                #pragma unroll
                for (int n = 0; n < 4; n++) {
                    float2 v;
                    v.x = o[mf][n][h*2]   * inv;
                    v.y = o[mf][n][h*2+1] * inv;
                    *(float2*)(orow + n*8 + lc) = v;
                }
            }
        }
    }
}

// ---------------- launch ----------------
extern "C" void kernel_launch(void* const* d_in, const int* in_sizes, int n_in,
                              void* d_out, int out_size)
{
    const float* x_in   = (const float*)d_in[0];
    const float* n1g    = (const float*)d_in[1];
    const float* n1b    = (const float*)d_in[2];
    const float* qkvw   = (const float*)d_in[3];
    const float* qkvb   = (const float*)d_in[4];
    const float* relb   = (const float*)d_in[5];
    const float* projw  = (const float*)d_in[6];
    const float* projb  = (const float*)d_in[7];
    const float* n2g    = (const float*)d_in[8];
    const float* n2b    = (const float*)d_in[9];
    const float* fc1w   = (const float*)d_in[10];
    const float* fc1b   = (const float*)d_in[11];
    const float* fc2w   = (const float*)d_in[12];
    const float* fc2b   = (const float*)d_in[13];
    float* out = (float*)d_out;

    float *px, *pxw, *pqkv, *paout, *pxn, *ph1, *pbm;
    cudaGetSymbolAddress((void**)&px,    g_x);
    cudaGetSymbolAddress((void**)&pxw,   g_xw);
    cudaGetSymbolAddress((void**)&pqkv,  g_qkv);
    cudaGetSymbolAddress((void**)&paout, g_aout);
    cudaGetSymbolAddress((void**)&pxn,   g_xn);
    cudaGetSymbolAddress((void**)&ph1,   g_h1);
    cudaGetSymbolAddress((void**)&pbm,   g_bm);

    cudaFuncSetAttribute(tc_gemm<EPI_STORE>,  cudaFuncAttributeMaxDynamicSharedMemorySize, TC_SMEM);
    cudaFuncSetAttribute(tc_gemm<EPI_PROJLN>, cudaFuncAttributeMaxDynamicSharedMemorySize, TC_SMEM);
    cudaFuncSetAttribute(tc_gemm<EPI_GELU>,   cudaFuncAttributeMaxDynamicSharedMemorySize, TC_SMEM);
    cudaFuncSetAttribute(tc_gemm<EPI_RES>,    cudaFuncAttributeMaxDynamicSharedMemorySize, TC_SMEM);

    int n4 = TOK*CDIM/4;
    copyk<<<1024, 256>>>((const float4*)x_in, (float4*)px, n4);

    const int MB = TOK/128;   // 343 exact
    for (int L = 0; L < 2; L++) {
        int shifted = L & 1;
        bias_prep<<<dim3(NTOK, 24), 128>>>(relb + (size_t)L*NBIAS*NHEAD, pbm);
        ln_part_kernel<<<TOK/4, 128>>>(px, pxw, n1g + L*CDIM, n1b + L*CDIM, shifted);
        tc_gemm<EPI_STORE><<<dim3(MB, QKVO/96), 256, TC_SMEM>>>(
            pxw, qkvw + (size_t)L*QKVO*CDIM, qkvb + L*QKVO, pqkv, nullptr, CDIM, QKVO, 0,
            nullptr, nullptr, nullptr);
        attn_mma_kernel<<<dim3(BN*NHEAD, 3), 128>>>(pqkv, paout, pbm, shifted);
        tc_gemm<EPI_PROJLN><<<dim3(MB, 1), 256, TC_SMEM>>>(
            paout, projw + (size_t)L*CDIM*CDIM, projb + L*CDIM, nullptr, px, CDIM, CDIM, shifted,
            n2g + L*CDIM, n2b + L*CDIM, pxn);
        tc_gemm<EPI_GELU><<<dim3(MB, FF/96), 256, TC_SMEM>>>(
            pxn, fc1w + (size_t)L*FF*CDIM, fc1b + L*FF, ph1, nullptr, CDIM, FF, 0,
            nullptr, nullptr, nullptr);
        tc_gemm<EPI_RES><<<dim3(MB, 1), 256, TC_SMEM>>>(
            ph1, fc2w + (size_t)L*CDIM*FF, fc2b + L*CDIM, (L == 1) ? out : nullptr, px, FF, CDIM, 0,
            nullptr, nullptr, nullptr);
    }
}

// round 13
// speedup vs baseline: 5.3192x; 1.0240x over previous
#include <cuda_runtime.h>
#include <cuda_fp16.h>
#include <math.h>
#include <stdint.h>

// ---------------- problem constants ----------------
#define BATCH 2
#define GRD 28
#define CDIM 96
#define NHEAD 3
#define HDIM 32
#define NTOK 343
#define NWIN 64
#define BN (BATCH*NWIN)
#define TOK (BATCH*GRD*GRD*GRD)   // 43904
#define QKVO (3*CDIM)   // 288
#define FF (4*CDIM)     // 384
#define NBIAS 2197
#define SCALE 0.17677669529663687f

// ---------------- scratch buffers ----------------
__device__ float g_x   [TOK*CDIM];
__device__ float g_qkv [TOK*QKVO];
__device__ float g_aout[TOK*CDIM];
__device__ float g_xn  [TOK*CDIM];
__device__ float g_h1  [TOK*FF];
__device__ float g_bm  [24*NTOK*NTOK + 16];

// ---------------- helpers ----------------
__device__ __forceinline__ uint32_t smem_u32(const void* p) {
    uint32_t a;
    asm("{ .reg .u64 t; cvta.to.shared.u64 t, %1; cvt.u32.u64 %0, t; }" : "=r"(a) : "l"(p));
    return a;
}
__device__ __forceinline__ void ldsm4(uint32_t* r, uint32_t addr) {
    asm volatile("ldmatrix.sync.aligned.m8n8.x4.shared.b16 {%0,%1,%2,%3}, [%4];"
        : "=r"(r[0]), "=r"(r[1]), "=r"(r[2]), "=r"(r[3]) : "r"(addr));
}
__device__ __forceinline__ void ldsm4t(uint32_t* r, uint32_t addr) {
    asm volatile("ldmatrix.sync.aligned.m8n8.x4.trans.shared.b16 {%0,%1,%2,%3}, [%4];"
        : "=r"(r[0]), "=r"(r[1]), "=r"(r[2]), "=r"(r[3]) : "r"(addr));
}
__device__ __forceinline__ void mma_fp16(float* c, const uint32_t* a, const uint32_t* b) {
    asm volatile("mma.sync.aligned.m16n8k16.row.col.f32.f16.f16.f32 "
        "{%0,%1,%2,%3}, {%4,%5,%6,%7}, {%8,%9}, {%0,%1,%2,%3};"
        : "+f"(c[0]), "+f"(c[1]), "+f"(c[2]), "+f"(c[3])
        : "r"(a[0]), "r"(a[1]), "r"(a[2]), "r"(a[3]), "r"(b[0]), "r"(b[1]));
}
__device__ __forceinline__ uint32_t packh2(float a, float b) {
    half2 h = __floats2half2_rn(a, b);
    return *(uint32_t*)&h;
}

// ---------------- bias+mask matrix precompute ----------------
__global__ __launch_bounds__(128) void bias_prep(
    const float* __restrict__ relb, float* __restrict__ BM)
{
    int qi = blockIdx.x;
    int hc = blockIdx.y;
    int head = hc >> 3, cls = hc & 7;
    int di = qi/49, rr = qi%49, hi = rr/7, wi = rr%7;
    int ri = ((cls&4) ? ((di<4)?1:2)*9 : 0)
           + ((cls&2) ? ((hi<4)?1:2)*3 : 0)
           + ((cls&1) ? ((wi<4)?1:2)   : 0);
    float* row = BM + ((size_t)hc*NTOK + qi)*NTOK;
    for (int j = threadIdx.x; j < NTOK; j += 128) {
        int dj = j/49, r2 = j%49, hj = r2/7, wj = r2%7;
        int bidx = (di-dj+6)*169 + (hi-hj+6)*13 + (wi-wj+6);
        float b = relb[bidx*NHEAD + head];
        int rj = ((cls&4) ? ((dj<4)?1:2)*9 : 0)
               + ((cls&2) ? ((hj<4)?1:2)*3 : 0)
               + ((cls&1) ? ((wj<4)?1:2)   : 0);
        if (ri != rj) b -= 100.f;
        row[j] = b;
    }
}

// ---------------- HMMA GEMM (fp16): Y = epi(X @ W^T + b) ----------------
#define LDB 104
#define A_OFF 0
#define B_OFF 26624
#define TC_SMEM 51200

#define EPI_STORE  0
#define EPI_PROJLN 1   // proj + window-reverse + residual + fused LN2
#define EPI_GELU   2
#define EPI_RES    3   // residual add (+ optional copy to Yout)

// LNA=1: A-staging applies shift+window-gather + LN1 (requires Kdim==96)
template<int EPI, int LNA>
__global__ __launch_bounds__(256, 2) void tc_gemm(
    const float* __restrict__ X, const float* __restrict__ W,
    const float* __restrict__ bias, float* __restrict__ Y,
    const float* __restrict__ xres_in, float* __restrict__ xres_out,
    int Kdim, int O, int shifted,
    const float* __restrict__ g2, const float* __restrict__ b2,
    float* __restrict__ xn_out)
{
    extern __shared__ char smem[];
    uint32_t sb = smem_u32(smem);
    int tid = threadIdx.x, wid = tid >> 5, lane = tid & 31;
    int m0 = blockIdx.x * 128, o0 = blockIdx.y * 96;
    int wm = (wid & 3) * 32, wn = (wid >> 2) * 48;

    float acc[2][6][4];
    #pragma unroll
    for (int i = 0; i < 2; i++)
        #pragma unroll
        for (int j = 0; j < 6; j++)
            #pragma unroll
            for (int t = 0; t < 4; t++) acc[i][j][t] = 0.f;

    int nch = LNA ? 1 : (Kdim / 96);
    for (int ch = 0; ch < nch; ch++) {
        int kc = ch * 96;
        if (ch) __syncthreads();
        if (LNA) {
            // ---- A staging: gather + LN1, 2 threads per row ----
            int row = tid >> 1, c0 = (tid & 1) * 48;
            int gm = m0 + row;
            int win = gm / NTOK, n = gm % NTOK;
            int b = win >> 6, wrem = win & 63;
            int bd = wrem >> 4, bh = (wrem >> 2) & 3, bw = wrem & 3;
            int ld = n / 49, rr2 = n % 49, lh = rr2 / 7, lw = rr2 % 7;
            int d = bd*7 + ld, h = bh*7 + lh, w = bw*7 + lw;
            if (shifted) {
                d += 3; if (d >= GRD) d -= GRD;
                h += 3; if (h >= GRD) h -= GRD;
                w += 3; if (w >= GRD) w -= GRD;
            }
            size_t srow = (size_t)(((b*GRD + d)*GRD + h)*GRD + w) * CDIM;
            float vbuf[48];
            float s = 0.f, ss = 0.f;
            #pragma unroll
            for (int i = 0; i < 12; i++) {
                float4 v = *(const float4*)(X + srow + c0 + i*4);
                vbuf[i*4] = v.x; vbuf[i*4+1] = v.y; vbuf[i*4+2] = v.z; vbuf[i*4+3] = v.w;
                s  += v.x + v.y + v.z + v.w;
                ss += v.x*v.x + v.y*v.y + v.z*v.z + v.w*v.w;
            }
            s  += __shfl_xor_sync(0xffffffffu, s, 1);
            ss += __shfl_xor_sync(0xffffffffu, ss, 1);
            float mean = s * (1.f/96.f);
            float var  = ss * (1.f/96.f) - mean*mean;
            float rstd = rsqrtf(var + 1e-5f);
            #pragma unroll
            for (int i = 0; i < 24; i++) {
                int c = c0 + i*2;
                float y0 = (vbuf[i*2]   - mean)*rstd*g2[c]   + b2[c];
                float y1 = (vbuf[i*2+1] - mean)*rstd*g2[c+1] + b2[c+1];
                *(uint32_t*)(smem + A_OFF + (uint32_t)(row*LDB + c)*2) = packh2(y0, y1);
            }
        } else {
            #pragma unroll
            for (int i = 0; i < 12; i++) {
                int e = tid + i*256;
                int m = e / 24, k = (e % 24) * 4;
                float4 v = *(const float4*)(X + (size_t)(m0 + m)*Kdim + kc + k);
                *(uint2*)(smem + A_OFF + (uint32_t)(m*LDB + k)*2) =
                    make_uint2(packh2(v.x, v.y), packh2(v.z, v.w));
            }
        }
        #pragma unroll
        for (int i = 0; i < 9; i++) {
            int e = tid + i*256;
            int r = e / 24, k = (e % 24) * 4;
            float4 v = *(const float4*)(W + (size_t)(o0 + r)*Kdim + kc + k);
            *(uint2*)(smem + B_OFF + (uint32_t)(r*LDB + k)*2) =
                make_uint2(packh2(v.x, v.y), packh2(v.z, v.w));
        }
        __syncthreads();

        #pragma unroll
        for (int ks = 0; ks < 6; ks++) {
            int k = ks * 16;
            uint32_t af[2][4];
            #pragma unroll
            for (int mf = 0; mf < 2; mf++) {
                int r = wm + mf*16 + (lane & 15);
                int c = k + ((lane >> 4) << 3);
                ldsm4(af[mf], sb + A_OFF + (uint32_t)(r*LDB + c)*2);
            }
            uint32_t bf[6][2];
            #pragma unroll
            for (int nq = 0; nq < 3; nq++) {
                int r = wn + nq*16 + (lane & 7) + ((lane >> 4) << 3);
                int c = k + (((lane >> 3) & 1) << 3);
                uint32_t t4[4];
                ldsm4(t4, sb + B_OFF + (uint32_t)(r*LDB + c)*2);
                bf[nq*2][0] = t4[0];  bf[nq*2][1] = t4[1];
                bf[nq*2+1][0] = t4[2]; bf[nq*2+1][1] = t4[3];
            }
            #pragma unroll
            for (int mf = 0; mf < 2; mf++)
                #pragma unroll
                for (int nf = 0; nf < 6; nf++)
                    mma_fp16(acc[mf][nf], af[mf], bf[nf]);
        }
    }
    __syncthreads();

    float* Dsm = (float*)smem;
    #pragma unroll
    for (int mf = 0; mf < 2; mf++) {
        int row = wm + mf*16 + (lane >> 2);
        #pragma unroll
        for (int nf = 0; nf < 6; nf++) {
            int col = wn + nf*8 + (lane & 3)*2;
            float b0 = bias[o0 + col], b1 = bias[o0 + col + 1];
            Dsm[row*100 + col]       = acc[mf][nf][0] + b0;
            Dsm[row*100 + col + 1]   = acc[mf][nf][1] + b1;
            Dsm[(row+8)*100 + col]   = acc[mf][nf][2] + b0;
            Dsm[(row+8)*100 + col+1] = acc[mf][nf][3] + b1;
        }
    }
    __syncthreads();

    if (EPI == EPI_PROJLN) {
        int row = tid >> 1, half = tid & 1, c0 = half * 48;
        int gm = m0 + row;
        int win = gm / NTOK, n = gm % NTOK;
        int b = win >> 6, wrem = win & 63;
        int bd = wrem >> 4, bh = (wrem >> 2) & 3, bw = wrem & 3;
        int ld = n / 49, rr2 = n % 49, lh = rr2 / 7, lw = rr2 % 7;
        int d = bd*7 + ld, h = bh*7 + lh, w = bw*7 + lw;
        if (shifted) {
            d += 3; if (d >= GRD) d -= GRD;
            h += 3; if (h >= GRD) h -= GRD;
            w += 3; if (w >= GRD) w -= GRD;
        }
        size_t drow = (size_t)(((b*GRD + d)*GRD + h)*GRD + w) * CDIM;
        float s = 0.f, ss = 0.f;
        #pragma unroll
        for (int i = 0; i < 12; i++) {
            int c = c0 + i*4;
            float4 v = *(const float4*)(Dsm + row*100 + c);
            float4 r = *(const float4*)(xres_in + drow + c);
            r.x += v.x; r.y += v.y; r.z += v.z; r.w += v.w;
            *(float4*)(Dsm + row*100 + c) = r;
            *(float4*)(xres_out + drow + c) = r;
            s  += r.x + r.y + r.z + r.w;
            ss += r.x*r.x + r.y*r.y + r.z*r.z + r.w*r.w;
        }
        s  += __shfl_xor_sync(0xffffffffu, s, 1);
        ss += __shfl_xor_sync(0xffffffffu, ss, 1);
        float mean = s * (1.f/96.f);
        float var  = ss * (1.f/96.f) - mean*mean;
        float rstd = rsqrtf(var + 1e-5f);
        float* nd = xn_out + drow;
        #pragma unroll
        for (int i = 0; i < 12; i++) {
            int c = c0 + i*4;
            float4 r = *(const float4*)(Dsm + row*100 + c);
            float4 y;
            y.x = (r.x - mean)*rstd*g2[c]   + b2[c];
            y.y = (r.y - mean)*rstd*g2[c+1] + b2[c+1];
            y.z = (r.z - mean)*rstd*g2[c+2] + b2[c+2];
            y.w = (r.w - mean)*rstd*g2[c+3] + b2[c+3];
            *(float4*)(nd + c) = y;
        }
    } else {
        #pragma unroll
        for (int i = 0; i < 12; i++) {
            int e = tid + i*256;
            int m = e / 24, c = (e % 24) * 4;
            float4 v = *(const float4*)(Dsm + m*100 + c);
            int gm = m0 + m, o = o0 + c;
            if (EPI == EPI_STORE) {
                *(float4*)(Y + (size_t)gm*O + o) = v;
            } else if (EPI == EPI_GELU) {
                v.x = 0.5f*v.x*(1.f + erff(v.x*0.70710678118654752f));
                v.y = 0.5f*v.y*(1.f + erff(v.y*0.70710678118654752f));
                v.z = 0.5f*v.z*(1.f + erff(v.z*0.70710678118654752f));
                v.w = 0.5f*v.w*(1.f + erff(v.w*0.70710678118654752f));
                *(float4*)(Y + (size_t)gm*O + o) = v;
            } else { // EPI_RES
                float4 r = *(const float4*)(xres_in + (size_t)gm*CDIM + o);
                r.x += v.x; r.y += v.y; r.z += v.z; r.w += v.w;
                *(float4*)(xres_out + (size_t)gm*CDIM + o) = r;
                if (Y) *(float4*)(Y + (size_t)gm*CDIM + o) = r;
            }
        }
    }
}

// ---------------- HMMA flash attention ----------------
#define QLD 40

__global__ __launch_bounds__(128) void attn_mma_kernel(
    const float* __restrict__ qkv, float* __restrict__ aout,
    const float* __restrict__ BM, int shifted)
{
    __shared__ half Qs[128*QLD];
    __shared__ half Ksm[64*QLD];
    __shared__ half Vs[64*QLD];
    uint32_t sQ = smem_u32(Qs), sK = smem_u32(Ksm), sV = smem_u32(Vs);

    int tid = threadIdx.x, wid = tid >> 5, lane = tid & 31;
    int bx = blockIdx.x;
    int win = bx / NHEAD, head = bx % NHEAD;
    int base = win * NTOK;
    int q0 = blockIdx.y * 128;
    int wrem = win & 63;
    int bd = wrem >> 4, bh = (wrem >> 2) & 3, bw = wrem & 3;
    int cls = shifted ? (((bd==3)<<2) | ((bh==3)<<1) | (bw==3)) : 0;
    const float* bmb = BM + (size_t)(head*8 + cls)*NTOK*NTOK;

    {
        int r = tid, qi = q0 + r;
        half2* dst = (half2*)(Qs + r*QLD);
        if (qi < NTOK) {
            const float4* src = (const float4*)(qkv + (size_t)(base+qi)*QKVO + head*HDIM);
            #pragma unroll
            for (int t = 0; t < 8; t++) {
                float4 v = src[t];
                dst[2*t]   = __floats2half2_rn(v.x*SCALE, v.y*SCALE);
                dst[2*t+1] = __floats2half2_rn(v.z*SCALE, v.w*SCALE);
            }
        } else {
            #pragma unroll
            for (int t = 0; t < 16; t++) dst[t] = __floats2half2_rn(0.f, 0.f);
        }
    }
    __syncthreads();

    int wm = wid * 32;
    uint32_t af[2][2][4];
    #pragma unroll
    for (int mf = 0; mf < 2; mf++)
        #pragma unroll
        for (int ks = 0; ks < 2; ks++) {
            int r = wm + mf*16 + (lane & 15);
            int c = ks*16 + ((lane >> 4) << 3);
            ldsm4(af[mf][ks], sQ + (uint32_t)(r*QLD + c)*2);
        }

    float o[2][4][4];
    #pragma unroll
    for (int mf = 0; mf < 2; mf++)
        #pragma unroll
        for (int n = 0; n < 4; n++)
            #pragma unroll
            for (int t = 0; t < 4; t++) o[mf][n][t] = 0.f;
    float mrun[2][2] = {{-1e30f,-1e30f},{-1e30f,-1e30f}};
    float lrun[2][2] = {{0.f,0.f},{0.f,0.f}};

    int lq = lane >> 2, lc = (lane & 3) * 2;

    for (int kt = 0; kt < 6; kt++) {
        if (kt) __syncthreads();
        // ---- stage K row / V row (row-major, identical layout) ----
        {
            int r = tid >> 1;
            int isV = tid & 1;
            int key = kt*64 + r;
            half2* kd = (half2*)((isV ? Vs : Ksm) + r*QLD);
            if (key < NTOK) {
                const float4* src = (const float4*)(qkv + (size_t)(base+key)*QKVO
                                                    + head*HDIM + (isV ? 2*CDIM : CDIM));
                #pragma unroll
                for (int t = 0; t < 8; t++) {
                    float4 v = src[t];
                    kd[2*t]   = __floats2half2_rn(v.x, v.y);
                    kd[2*t+1] = __floats2half2_rn(v.z, v.w);
                }
            } else {
                #pragma unroll
                for (int t = 0; t < 16; t++) kd[t] = __floats2half2_rn(0.f, 0.f);
            }
        }
        __syncthreads();

        // ---- S = Q K^T ----
        float sf[2][8][4];
        #pragma unroll
        for (int mf = 0; mf < 2; mf++)
            #pragma unroll
            for (int nf = 0; nf < 8; nf++)
                #pragma unroll
                for (int t = 0; t < 4; t++) sf[mf][nf][t] = 0.f;
        #pragma unroll
        for (int ks = 0; ks < 2; ks++) {
            uint32_t bf[8][2];
            #pragma unroll
            for (int nq = 0; nq < 4; nq++) {
                int r = nq*16 + (lane & 7) + ((lane >> 4) << 3);
                int c = ks*16 + (((lane >> 3) & 1) << 3);
                uint32_t t4[4];
                ldsm4(t4, sK + (uint32_t)(r*QLD + c)*2);
                bf[nq*2][0] = t4[0];  bf[nq*2][1] = t4[1];
                bf[nq*2+1][0] = t4[2]; bf[nq*2+1][1] = t4[3];
            }
            #pragma unroll
            for (int mf = 0; mf < 2; mf++)
                #pragma unroll
                for (int nf = 0; nf < 8; nf++)
                    mma_fp16(sf[mf][nf], af[mf][ks], bf[nf]);
        }

        // ---- bias + mask + online softmax ----
        #pragma unroll
        for (int mf = 0; mf < 2; mf++) {
            #pragma unroll
            for (int h = 0; h < 2; h++) {
                int qi = q0 + wm + mf*16 + h*8 + lq;
                bool qv = qi < NTOK;
                const float* bmrow = bmb + (size_t)(qv ? qi : 0)*NTOK;
                float vmax = -1e30f;
                #pragma unroll
                for (int nf = 0; nf < 8; nf++) {
                    #pragma unroll
                    for (int u = 0; u < 2; u++) {
                        int j = kt*64 + nf*8 + lc + u;
                        float s = sf[mf][nf][h*2+u];
                        s = (qv && j < NTOK) ? s + bmrow[j] : -1e30f;
                        sf[mf][nf][h*2+u] = s;
                        vmax = fmaxf(vmax, s);
                    }
                }
                vmax = fmaxf(vmax, __shfl_xor_sync(0xffffffffu, vmax, 1));
                vmax = fmaxf(vmax, __shfl_xor_sync(0xffffffffu, vmax, 2));
                float mnew = fmaxf(mrun[mf][h], vmax);
                float al = __expf(mrun[mf][h] - mnew);
                mrun[mf][h] = mnew;
                float ls = 0.f;
                #pragma unroll
                for (int nf = 0; nf < 8; nf++) {
                    #pragma unroll
                    for (int u = 0; u < 2; u++) {
                        float p = __expf(sf[mf][nf][h*2+u] - mnew);
                        sf[mf][nf][h*2+u] = p;
                        ls += p;
                    }
                }
                lrun[mf][h] = lrun[mf][h]*al + ls;
                #pragma unroll
                for (int n = 0; n < 4; n++) {
                    o[mf][n][h*2]   *= al;
                    o[mf][n][h*2+1] *= al;
                }
            }
        }

        // ---- O += P V  (V row-major + ldmatrix.trans) ----
        #pragma unroll
        for (int ks4 = 0; ks4 < 4; ks4++) {
            uint32_t bv[4][2];
            #pragma unroll
            for (int g = 0; g < 2; g++) {
                int r = ks4*16 + (lane & 15);
                int c = g*16 + ((lane >> 4) << 3);
                uint32_t t4[4];
                ldsm4t(t4, sV + (uint32_t)(r*QLD + c)*2);
                bv[g*2][0] = t4[0];  bv[g*2][1] = t4[1];
                bv[g*2+1][0] = t4[2]; bv[g*2+1][1] = t4[3];
            }
            #pragma unroll
            for (int mf = 0; mf < 2; mf++) {
                uint32_t pa[4];
                pa[0] = packh2(sf[mf][2*ks4][0],   sf[mf][2*ks4][1]);
                pa[1] = packh2(sf[mf][2*ks4][2],   sf[mf][2*ks4][3]);
                pa[2] = packh2(sf[mf][2*ks4+1][0], sf[mf][2*ks4+1][1]);
                pa[3] = packh2(sf[mf][2*ks4+1][2], sf[mf][2*ks4+1][3]);
                #pragma unroll
                for (int n = 0; n < 4; n++)
                    mma_fp16(o[mf][n], pa, bv[n]);
            }
        }
    }

    #pragma unroll
    for (int mf = 0; mf < 2; mf++) {
        #pragma unroll
        for (int h = 0; h < 2; h++) {
            float l = lrun[mf][h];
            l += __shfl_xor_sync(0xffffffffu, l, 1);
            l += __shfl_xor_sync(0xffffffffu, l, 2);
            float inv = 1.f / l;
            int qi = q0 + wm + mf*16 + h*8 + lq;
            if (qi < NTOK) {
                float* orow = aout + (size_t)(base+qi)*CDIM + head*HDIM;
                #pragma unroll
                for (int n = 0; n < 4; n++) {
                    float2 v;
                    v.x = o[mf][n][h*2]   * inv;
                    v.y = o[mf][n][h*2+1] * inv;
                    *(float2*)(orow + n*8 + lc) = v;
                }
            }
        }
    }
}

// ---------------- launch ----------------
extern "C" void kernel_launch(void* const* d_in, const int* in_sizes, int n_in,
                              void* d_out, int out_size)
{
    const float* x_in   = (const float*)d_in[0];
    const float* n1g    = (const float*)d_in[1];
    const float* n1b    = (const float*)d_in[2];
    const float* qkvw   = (const float*)d_in[3];
    const float* qkvb   = (const float*)d_in[4];
    const float* relb   = (const float*)d_in[5];
    const float* projw  = (const float*)d_in[6];
    const float* projb  = (const float*)d_in[7];
    const float* n2g    = (const float*)d_in[8];
    const float* n2b    = (const float*)d_in[9];
    const float* fc1w   = (const float*)d_in[10];
    const float* fc1b   = (const float*)d_in[11];
    const float* fc2w   = (const float*)d_in[12];
    const float* fc2b   = (const float*)d_in[13];
    float* out = (float*)d_out;

    float *px, *pqkv, *paout, *pxn, *ph1, *pbm;
    cudaGetSymbolAddress((void**)&px,    g_x);
    cudaGetSymbolAddress((void**)&pqkv,  g_qkv);
    cudaGetSymbolAddress((void**)&paout, g_aout);
    cudaGetSymbolAddress((void**)&pxn,   g_xn);
    cudaGetSymbolAddress((void**)&ph1,   g_h1);
    cudaGetSymbolAddress((void**)&pbm,   g_bm);

    cudaFuncSetAttribute(tc_gemm<EPI_STORE,1>,  cudaFuncAttributeMaxDynamicSharedMemorySize, TC_SMEM);
    cudaFuncSetAttribute(tc_gemm<EPI_PROJLN,0>, cudaFuncAttributeMaxDynamicSharedMemorySize, TC_SMEM);
    cudaFuncSetAttribute(tc_gemm<EPI_GELU,0>,   cudaFuncAttributeMaxDynamicSharedMemorySize, TC_SMEM);
    cudaFuncSetAttribute(tc_gemm<EPI_RES,0>,    cudaFuncAttributeMaxDynamicSharedMemorySize, TC_SMEM);

    const int MB = TOK/128;   // 343 exact
    for (int L = 0; L < 2; L++) {
        int shifted = L & 1;
        const float* xsrc = (L == 0) ? x_in : px;
        bias_prep<<<dim3(NTOK, 24), 128>>>(relb + (size_t)L*NBIAS*NHEAD, pbm);
        // QKV GEMM with fused LN1 + shift + window gather
        tc_gemm<EPI_STORE,1><<<dim3(MB, QKVO/96), 256, TC_SMEM>>>(
            xsrc, qkvw + (size_t)L*QKVO*CDIM, qkvb + L*QKVO, pqkv,
            nullptr, nullptr, CDIM, QKVO, shifted,
            n1g + L*CDIM, n1b + L*CDIM, nullptr);
        attn_mma_kernel<<<dim3(BN*NHEAD, 3), 128>>>(pqkv, paout, pbm, shifted);
        tc_gemm<EPI_PROJLN,0><<<dim3(MB, 1), 256, TC_SMEM>>>(
            paout, projw + (size_t)L*CDIM*CDIM, projb + L*CDIM, nullptr,
            xsrc, px, CDIM, CDIM, shifted,
            n2g + L*CDIM, n2b + L*CDIM, pxn);
        tc_gemm<EPI_GELU,0><<<dim3(MB, FF/96), 256, TC_SMEM>>>(
            pxn, fc1w + (size_t)L*FF*CDIM, fc1b + L*FF, ph1,
            nullptr, nullptr, CDIM, FF, 0,
            nullptr, nullptr, nullptr);
        tc_gemm<EPI_RES,0><<<dim3(MB, 1), 256, TC_SMEM>>>(
            ph1, fc2w + (size_t)L*CDIM*FF, fc2b + L*CDIM, (L == 1) ? out : nullptr,
            px, px, FF, CDIM, 0,
            nullptr, nullptr, nullptr);
    }
}

// round 14
// speedup vs baseline: 6.9766x; 1.3116x over previous
#include <cuda_runtime.h>
#include <cuda_fp16.h>
#include <math.h>
#include <stdint.h>

// ---------------- problem constants ----------------
#define BATCH 2
#define GRD 28
#define CDIM 96
#define NHEAD 3
#define HDIM 32
#define NTOK 343
#define NWIN 64
#define BN (BATCH*NWIN)
#define TOK (BATCH*GRD*GRD*GRD)   // 43904
#define QKVO (3*CDIM)   // 288
#define FF (4*CDIM)     // 384
#define NBIAS 2197
#define BMLD 344        // padded BM row stride (halves)
#define SCALE 0.17677669529663687f

// ---------------- scratch buffers ----------------
__device__ float  g_x   [TOK*CDIM];
__device__ __half g_qkv [TOK*QKVO];
__device__ __half g_aout[TOK*CDIM];
__device__ __half g_xn  [TOK*CDIM];
__device__ __half g_h1  [TOK*FF];
__device__ __half g_bm  [24*NTOK*BMLD + 16];

// ---------------- helpers ----------------
__device__ __forceinline__ uint32_t smem_u32(const void* p) {
    uint32_t a;
    asm("{ .reg .u64 t; cvta.to.shared.u64 t, %1; cvt.u32.u64 %0, t; }" : "=r"(a) : "l"(p));
    return a;
}
__device__ __forceinline__ void ldsm4(uint32_t* r, uint32_t addr) {
    asm volatile("ldmatrix.sync.aligned.m8n8.x4.shared.b16 {%0,%1,%2,%3}, [%4];"
        : "=r"(r[0]), "=r"(r[1]), "=r"(r[2]), "=r"(r[3]) : "r"(addr));
}
__device__ __forceinline__ void ldsm4t(uint32_t* r, uint32_t addr) {
    asm volatile("ldmatrix.sync.aligned.m8n8.x4.trans.shared.b16 {%0,%1,%2,%3}, [%4];"
        : "=r"(r[0]), "=r"(r[1]), "=r"(r[2]), "=r"(r[3]) : "r"(addr));
}
__device__ __forceinline__ void mma_fp16(float* c, const uint32_t* a, const uint32_t* b) {
    asm volatile("mma.sync.aligned.m16n8k16.row.col.f32.f16.f16.f32 "
        "{%0,%1,%2,%3}, {%4,%5,%6,%7}, {%8,%9}, {%0,%1,%2,%3};"
        : "+f"(c[0]), "+f"(c[1]), "+f"(c[2]), "+f"(c[3])
        : "r"(a[0]), "r"(a[1]), "r"(a[2]), "r"(a[3]), "r"(b[0]), "r"(b[1]));
}
__device__ __forceinline__ uint32_t packh2(float a, float b) {
    half2 h = __floats2half2_rn(a, b);
    return *(uint32_t*)&h;
}

// ---------------- bias+mask matrix precompute (half, padded rows) ----------------
__global__ __launch_bounds__(128) void bias_prep(
    const float* __restrict__ relb, __half* __restrict__ BM, int allcls)
{
    int qi = blockIdx.x;
    int hc = allcls ? blockIdx.y : (blockIdx.y << 3);   // cls=0 only when !allcls
    int head = hc >> 3, cls = hc & 7;
    int di = qi/49, rr = qi%49, hi = rr/7, wi = rr%7;
    int ri = ((cls&4) ? ((di<4)?1:2)*9 : 0)
           + ((cls&2) ? ((hi<4)?1:2)*3 : 0)
           + ((cls&1) ? ((wi<4)?1:2)   : 0);
    __half* row = BM + ((size_t)hc*NTOK + qi)*BMLD;
    for (int j = threadIdx.x; j < NTOK; j += 128) {
        int dj = j/49, r2 = j%49, hj = r2/7, wj = r2%7;
        int bidx = (di-dj+6)*169 + (hi-hj+6)*13 + (wi-wj+6);
        float b = relb[bidx*NHEAD + head];
        int rj = ((cls&4) ? ((dj<4)?1:2)*9 : 0)
               + ((cls&2) ? ((hj<4)?1:2)*3 : 0)
               + ((cls&1) ? ((wj<4)?1:2)   : 0);
        if (ri != rj) b -= 100.f;
        row[j] = __float2half(b);
    }
}

// ---------------- HMMA GEMM (fp16): Y = epi(X @ W^T + b) ----------------
#define LDB 104
#define A_OFF 0
#define B_OFF 26624
#define TC_SMEM 51200

#define EPI_STORE  0   // Y is half*
#define EPI_PROJLN 1   // proj + window-reverse + residual + fused LN2 (xn half)
#define EPI_GELU   2   // Y is half*
#define EPI_RES    3   // residual add, optional fp32 copy to Yout

// LNA=1: A-staging applies shift+window-gather + LN1 from fp32 X (Kdim==96)
// AH=1:  X is half* (straight copy staging)
template<int EPI, int LNA, int AH>
__global__ __launch_bounds__(256, 2) void tc_gemm(
    const void* __restrict__ Xv, const float* __restrict__ W,
    const float* __restrict__ bias, void* __restrict__ Yv,
    const float* __restrict__ xres_in, float* __restrict__ xres_out,
    int Kdim, int O, int shifted,
    const float* __restrict__ g2, const float* __restrict__ b2,
    __half* __restrict__ xn_out)
{
    extern __shared__ char smem[];
    uint32_t sb = smem_u32(smem);
    int tid = threadIdx.x, wid = tid >> 5, lane = tid & 31;
    int m0 = blockIdx.x * 128, o0 = blockIdx.y * 96;
    int wm = (wid & 3) * 32, wn = (wid >> 2) * 48;

    float acc[2][6][4];
    #pragma unroll
    for (int i = 0; i < 2; i++)
        #pragma unroll
        for (int j = 0; j < 6; j++)
            #pragma unroll
            for (int t = 0; t < 4; t++) acc[i][j][t] = 0.f;

    int nch = LNA ? 1 : (Kdim / 96);
    for (int ch = 0; ch < nch; ch++) {
        int kc = ch * 96;
        if (ch) __syncthreads();
        if (LNA) {
            const float* X = (const float*)Xv;
            int row = tid >> 1, c0 = (tid & 1) * 48;
            int gm = m0 + row;
            int win = gm / NTOK, n = gm % NTOK;
            int b = win >> 6, wrem = win & 63;
            int bd = wrem >> 4, bh = (wrem >> 2) & 3, bw = wrem & 3;
            int ld = n / 49, rr2 = n % 49, lh = rr2 / 7, lw = rr2 % 7;
            int d = bd*7 + ld, h = bh*7 + lh, w = bw*7 + lw;
            if (shifted) {
                d += 3; if (d >= GRD) d -= GRD;
                h += 3; if (h >= GRD) h -= GRD;
                w += 3; if (w >= GRD) w -= GRD;
            }
            size_t srow = (size_t)(((b*GRD + d)*GRD + h)*GRD + w) * CDIM;
            float vbuf[48];
            float s = 0.f, ss = 0.f;
            #pragma unroll
            for (int i = 0; i < 12; i++) {
                float4 v = *(const float4*)(X + srow + c0 + i*4);
                vbuf[i*4] = v.x; vbuf[i*4+1] = v.y; vbuf[i*4+2] = v.z; vbuf[i*4+3] = v.w;
                s  += v.x + v.y + v.z + v.w;
                ss += v.x*v.x + v.y*v.y + v.z*v.z + v.w*v.w;
            }
            s  += __shfl_xor_sync(0xffffffffu, s, 1);
            ss += __shfl_xor_sync(0xffffffffu, ss, 1);
            float mean = s * (1.f/96.f);
            float var  = ss * (1.f/96.f) - mean*mean;
            float rstd = rsqrtf(var + 1e-5f);
            #pragma unroll
            for (int i = 0; i < 24; i++) {
                int c = c0 + i*2;
                float y0 = (vbuf[i*2]   - mean)*rstd*g2[c]   + b2[c];
                float y1 = (vbuf[i*2+1] - mean)*rstd*g2[c+1] + b2[c+1];
                *(uint32_t*)(smem + A_OFF + (uint32_t)(row*LDB + c)*2) = packh2(y0, y1);
            }
        } else if (AH) {
            const __half* X = (const __half*)Xv;
            #pragma unroll
            for (int i = 0; i < 12; i++) {
                int e = tid + i*256;
                int m = e / 24, k = (e % 24) * 4;
                *(uint2*)(smem + A_OFF + (uint32_t)(m*LDB + k)*2) =
                    *(const uint2*)(X + (size_t)(m0 + m)*Kdim + kc + k);
            }
        } else {
            const float* X = (const float*)Xv;
            #pragma unroll
            for (int i = 0; i < 12; i++) {
                int e = tid + i*256;
                int m = e / 24, k = (e % 24) * 4;
                float4 v = *(const float4*)(X + (size_t)(m0 + m)*Kdim + kc + k);
                *(uint2*)(smem + A_OFF + (uint32_t)(m*LDB + k)*2) =
                    make_uint2(packh2(v.x, v.y), packh2(v.z, v.w));
            }
        }
        #pragma unroll
        for (int i = 0; i < 9; i++) {
            int e = tid + i*256;
            int r = e / 24, k = (e % 24) * 4;
            float4 v = *(const float4*)(W + (size_t)(o0 + r)*Kdim + kc + k);
            *(uint2*)(smem + B_OFF + (uint32_t)(r*LDB + k)*2) =
                make_uint2(packh2(v.x, v.y), packh2(v.z, v.w));
        }
        __syncthreads();

        #pragma unroll
        for (int ks = 0; ks < 6; ks++) {
            int k = ks * 16;
            uint32_t af[2][4];
            #pragma unroll
            for (int mf = 0; mf < 2; mf++) {
                int r = wm + mf*16 + (lane & 15);
                int c = k + ((lane >> 4) << 3);
                ldsm4(af[mf], sb + A_OFF + (uint32_t)(r*LDB + c)*2);
            }
            uint32_t bf[6][2];
            #pragma unroll
            for (int nq = 0; nq < 3; nq++) {
                int r = wn + nq*16 + (lane & 7) + ((lane >> 4) << 3);
                int c = k + (((lane >> 3) & 1) << 3);
                uint32_t t4[4];
                ldsm4(t4, sb + B_OFF + (uint32_t)(r*LDB + c)*2);
                bf[nq*2][0] = t4[0];  bf[nq*2][1] = t4[1];
                bf[nq*2+1][0] = t4[2]; bf[nq*2+1][1] = t4[3];
            }
            #pragma unroll
            for (int mf = 0; mf < 2; mf++)
                #pragma unroll
                for (int nf = 0; nf < 6; nf++)
                    mma_fp16(acc[mf][nf], af[mf], bf[nf]);
        }
    }
    __syncthreads();

    float* Dsm = (float*)smem;
    #pragma unroll
    for (int mf = 0; mf < 2; mf++) {
        int row = wm + mf*16 + (lane >> 2);
        #pragma unroll
        for (int nf = 0; nf < 6; nf++) {
            int col = wn + nf*8 + (lane & 3)*2;
            float b0 = bias[o0 + col], b1 = bias[o0 + col + 1];
            Dsm[row*100 + col]       = acc[mf][nf][0] + b0;
            Dsm[row*100 + col + 1]   = acc[mf][nf][1] + b1;
            Dsm[(row+8)*100 + col]   = acc[mf][nf][2] + b0;
            Dsm[(row+8)*100 + col+1] = acc[mf][nf][3] + b1;
        }
    }
    __syncthreads();

    if (EPI == EPI_PROJLN) {
        int row = tid >> 1, half_ = tid & 1, c0 = half_ * 48;
        int gm = m0 + row;
        int win = gm / NTOK, n = gm % NTOK;
        int b = win >> 6, wrem = win & 63;
        int bd = wrem >> 4, bh = (wrem >> 2) & 3, bw = wrem & 3;
        int ld = n / 49, rr2 = n % 49, lh = rr2 / 7, lw = rr2 % 7;
        int d = bd*7 + ld, h = bh*7 + lh, w = bw*7 + lw;
        if (shifted) {
            d += 3; if (d >= GRD) d -= GRD;
            h += 3; if (h >= GRD) h -= GRD;
            w += 3; if (w >= GRD) w -= GRD;
        }
        size_t drow = (size_t)(((b*GRD + d)*GRD + h)*GRD + w) * CDIM;
        float s = 0.f, ss = 0.f;
        #pragma unroll
        for (int i = 0; i < 12; i++) {
            int c = c0 + i*4;
            float4 v = *(const float4*)(Dsm + row*100 + c);
            float4 r = *(const float4*)(xres_in + drow + c);
            r.x += v.x; r.y += v.y; r.z += v.z; r.w += v.w;
            *(float4*)(Dsm + row*100 + c) = r;
            *(float4*)(xres_out + drow + c) = r;
            s  += r.x + r.y + r.z + r.w;
            ss += r.x*r.x + r.y*r.y + r.z*r.z + r.w*r.w;
        }
        s  += __shfl_xor_sync(0xffffffffu, s, 1);
        ss += __shfl_xor_sync(0xffffffffu, ss, 1);
        float mean = s * (1.f/96.f);
        float var  = ss * (1.f/96.f) - mean*mean;
        float rstd = rsqrtf(var + 1e-5f);
        __half* nd = xn_out + drow;
        #pragma unroll
        for (int i = 0; i < 12; i++) {
            int c = c0 + i*4;
            float4 r = *(const float4*)(Dsm + row*100 + c);
            float y0 = (r.x - mean)*rstd*g2[c]   + b2[c];
            float y1 = (r.y - mean)*rstd*g2[c+1] + b2[c+1];
            float y2 = (r.z - mean)*rstd*g2[c+2] + b2[c+2];
            float y3 = (r.w - mean)*rstd*g2[c+3] + b2[c+3];
            *(uint2*)(nd + c) = make_uint2(packh2(y0, y1), packh2(y2, y3));
        }
    } else {
        #pragma unroll
        for (int i = 0; i < 12; i++) {
            int e = tid + i*256;
            int m = e / 24, c = (e % 24) * 4;
            float4 v = *(const float4*)(Dsm + m*100 + c);
            int gm = m0 + m, o = o0 + c;
            if (EPI == EPI_STORE) {
                *(uint2*)((__half*)Yv + (size_t)gm*O + o) =
                    make_uint2(packh2(v.x, v.y), packh2(v.z, v.w));
            } else if (EPI == EPI_GELU) {
                v.x = 0.5f*v.x*(1.f + erff(v.x*0.70710678118654752f));
                v.y = 0.5f*v.y*(1.f + erff(v.y*0.70710678118654752f));
                v.z = 0.5f*v.z*(1.f + erff(v.z*0.70710678118654752f));
                v.w = 0.5f*v.w*(1.f + erff(v.w*0.70710678118654752f));
                *(uint2*)((__half*)Yv + (size_t)gm*O + o) =
                    make_uint2(packh2(v.x, v.y), packh2(v.z, v.w));
            } else { // EPI_RES
                float4 r = *(const float4*)(xres_in + (size_t)gm*CDIM + o);
                r.x += v.x; r.y += v.y; r.z += v.z; r.w += v.w;
                *(float4*)(xres_out + (size_t)gm*CDIM + o) = r;
                if (Yv) *(float4*)((float*)Yv + (size_t)gm*CDIM + o) = r;
            }
        }
    }
}

// ---------------- HMMA flash attention (half I/O) ----------------
#define QLD 40

__global__ __launch_bounds__(128) void attn_mma_kernel(
    const __half* __restrict__ qkv, __half* __restrict__ aout,
    const __half* __restrict__ BM, int shifted)
{
    __shared__ half Qs[128*QLD];
    __shared__ half Ksm[64*QLD];
    __shared__ half Vs[64*QLD];
    uint32_t sQ = smem_u32(Qs), sK = smem_u32(Ksm), sV = smem_u32(Vs);

    int tid = threadIdx.x, wid = tid >> 5, lane = tid & 31;
    int bx = blockIdx.x;
    int win = bx / NHEAD, head = bx % NHEAD;
    int base = win * NTOK;
    int q0 = blockIdx.y * 128;
    int wrem = win & 63;
    int bd = wrem >> 4, bh = (wrem >> 2) & 3, bw = wrem & 3;
    int cls = shifted ? (((bd==3)<<2) | ((bh==3)<<1) | (bw==3)) : 0;
    const __half* bmb = BM + (size_t)(head*8 + cls)*NTOK*BMLD;

    {
        int r = tid, qi = q0 + r;
        half2* dst = (half2*)(Qs + r*QLD);
        if (qi < NTOK) {
            const half2* src = (const half2*)(qkv + (size_t)(base+qi)*QKVO + head*HDIM);
            #pragma unroll
            for (int t = 0; t < 16; t++) {
                float2 f = __half22float2(src[t]);
                dst[t] = __floats2half2_rn(f.x*SCALE, f.y*SCALE);
            }
        } else {
            #pragma unroll
            for (int t = 0; t < 16; t++) dst[t] = __floats2half2_rn(0.f, 0.f);
        }
    }
    __syncthreads();

    int wm = wid * 32;
    uint32_t af[2][2][4];
    #pragma unroll
    for (int mf = 0; mf < 2; mf++)
        #pragma unroll
        for (int ks = 0; ks < 2; ks++) {
            int r = wm + mf*16 + (lane & 15);
            int c = ks*16 + ((lane >> 4) << 3);
            ldsm4(af[mf][ks], sQ + (uint32_t)(r*QLD + c)*2);
        }

    float o[2][4][4];
    #pragma unroll
    for (int mf = 0; mf < 2; mf++)
        #pragma unroll
        for (int n = 0; n < 4; n++)
            #pragma unroll
            for (int t = 0; t < 4; t++) o[mf][n][t] = 0.f;
    float mrun[2][2] = {{-1e30f,-1e30f},{-1e30f,-1e30f}};
    float lrun[2][2] = {{0.f,0.f},{0.f,0.f}};

    int lq = lane >> 2, lc = (lane & 3) * 2;

    for (int kt = 0; kt < 6; kt++) {
        if (kt) __syncthreads();
        {
            int r = tid >> 1;
            int isV = tid & 1;
            int key = kt*64 + r;
            uint4* kd = (uint4*)((isV ? Vs : Ksm) + r*QLD);
            if (key < NTOK) {
                const uint4* src = (const uint4*)(qkv + (size_t)(base+key)*QKVO
                                                  + head*HDIM + (isV ? 2*CDIM : CDIM));
                kd[0] = src[0]; kd[1] = src[1]; kd[2] = src[2]; kd[3] = src[3];
            } else {
                uint4 z = make_uint4(0,0,0,0);
                kd[0] = z; kd[1] = z; kd[2] = z; kd[3] = z;
            }
        }
        __syncthreads();

        float sf[2][8][4];
        #pragma unroll
        for (int mf = 0; mf < 2; mf++)
            #pragma unroll
            for (int nf = 0; nf < 8; nf++)
                #pragma unroll
                for (int t = 0; t < 4; t++) sf[mf][nf][t] = 0.f;
        #pragma unroll
        for (int ks = 0; ks < 2; ks++) {
            uint32_t bf[8][2];
            #pragma unroll
            for (int nq = 0; nq < 4; nq++) {
                int r = nq*16 + (lane & 7) + ((lane >> 4) << 3);
                int c = ks*16 + (((lane >> 3) & 1) << 3);
                uint32_t t4[4];
                ldsm4(t4, sK + (uint32_t)(r*QLD + c)*2);
                bf[nq*2][0] = t4[0];  bf[nq*2][1] = t4[1];
                bf[nq*2+1][0] = t4[2]; bf[nq*2+1][1] = t4[3];
            }
            #pragma unroll
            for (int mf = 0; mf < 2; mf++)
                #pragma unroll
                for (int nf = 0; nf < 8; nf++)
                    mma_fp16(sf[mf][nf], af[mf][ks], bf[nf]);
        }

        #pragma unroll
        for (int mf = 0; mf < 2; mf++) {
            #pragma unroll
            for (int h = 0; h < 2; h++) {
                int qi = q0 + wm + mf*16 + h*8 + lq;
                bool qv = qi < NTOK;
                const __half* bmrow = bmb + (size_t)(qv ? qi : 0)*BMLD;
                float vmax = -1e30f;
                #pragma unroll
                for (int nf = 0; nf < 8; nf++) {
                    int j = kt*64 + nf*8 + lc;
                    float2 bb = make_float2(0.f, 0.f);
                    if (qv && j < NTOK) bb = __half22float2(*(const half2*)(bmrow + j));
                    float s0 = sf[mf][nf][h*2];
                    float s1 = sf[mf][nf][h*2+1];
                    s0 = (qv && j < NTOK)     ? s0 + bb.x : -1e30f;
                    s1 = (qv && j+1 < NTOK)   ? s1 + bb.y : -1e30f;
                    sf[mf][nf][h*2]   = s0;
                    sf[mf][nf][h*2+1] = s1;
                    vmax = fmaxf(vmax, fmaxf(s0, s1));
                }
                vmax = fmaxf(vmax, __shfl_xor_sync(0xffffffffu, vmax, 1));
                vmax = fmaxf(vmax, __shfl_xor_sync(0xffffffffu, vmax, 2));
                float mnew = fmaxf(mrun[mf][h], vmax);
                float al = __expf(mrun[mf][h] - mnew);
                mrun[mf][h] = mnew;
                float ls = 0.f;
                #pragma unroll
                for (int nf = 0; nf < 8; nf++) {
                    #pragma unroll
                    for (int u = 0; u < 2; u++) {
                        float p = __expf(sf[mf][nf][h*2+u] - mnew);
                        sf[mf][nf][h*2+u] = p;
                        ls += p;
                    }
                }
                lrun[mf][h] = lrun[mf][h]*al + ls;
                #pragma unroll
                for (int n = 0; n < 4; n++) {
                    o[mf][n][h*2]   *= al;
                    o[mf][n][h*2+1] *= al;
                }
            }
        }

        #pragma unroll
        for (int ks4 = 0; ks4 < 4; ks4++) {
            uint32_t bv[4][2];
            #pragma unroll
            for (int g = 0; g < 2; g++) {
                int r = ks4*16 + (lane & 15);
                int c = g*16 + ((lane >> 4) << 3);
                uint32_t t4[4];
                ldsm4t(t4, sV + (uint32_t)(r*QLD + c)*2);
                bv[g*2][0] = t4[0];  bv[g*2][1] = t4[1];
                bv[g*2+1][0] = t4[2]; bv[g*2+1][1] = t4[3];
            }
            #pragma unroll
            for (int mf = 0; mf < 2; mf++) {
                uint32_t pa[4];
                pa[0] = packh2(sf[mf][2*ks4][0],   sf[mf][2*ks4][1]);
                pa[1] = packh2(sf[mf][2*ks4][2],   sf[mf][2*ks4][3]);
                pa[2] = packh2(sf[mf][2*ks4+1][0], sf[mf][2*ks4+1][1]);
                pa[3] = packh2(sf[mf][2*ks4+1][2], sf[mf][2*ks4+1][3]);
                #pragma unroll
                for (int n = 0; n < 4; n++)
                    mma_fp16(o[mf][n], pa, bv[n]);
            }
        }
    }

    #pragma unroll
    for (int mf = 0; mf < 2; mf++) {
        #pragma unroll
        for (int h = 0; h < 2; h++) {
            float l = lrun[mf][h];
            l += __shfl_xor_sync(0xffffffffu, l, 1);
            l += __shfl_xor_sync(0xffffffffu, l, 2);
            float inv = 1.f / l;
            int qi = q0 + wm + mf*16 + h*8 + lq;
            if (qi < NTOK) {
                __half* orow = aout + (size_t)(base+qi)*CDIM + head*HDIM;
                #pragma unroll
                for (int n = 0; n < 4; n++)
                    *(uint32_t*)(orow + n*8 + lc) =
                        packh2(o[mf][n][h*2]*inv, o[mf][n][h*2+1]*inv);
            }
        }
    }
}

// ---------------- launch ----------------
extern "C" void kernel_launch(void* const* d_in, const int* in_sizes, int n_in,
                              void* d_out, int out_size)
{
    const float* x_in   = (const float*)d_in[0];
    const float* n1g    = (const float*)d_in[1];
    const float* n1b    = (const float*)d_in[2];
    const float* qkvw   = (const float*)d_in[3];
    const float* qkvb   = (const float*)d_in[4];
    const float* relb   = (const float*)d_in[5];
    const float* projw  = (const float*)d_in[6];
    const float* projb  = (const float*)d_in[7];
    const float* n2g    = (const float*)d_in[8];
    const float* n2b    = (const float*)d_in[9];
    const float* fc1w   = (const float*)d_in[10];
    const float* fc1b   = (const float*)d_in[11];
    const float* fc2w   = (const float*)d_in[12];
    const float* fc2b   = (const float*)d_in[13];
    float* out = (float*)d_out;

    float *px;
    __half *pqkv, *paout, *pxn, *ph1, *pbm;
    cudaGetSymbolAddress((void**)&px,    g_x);
    cudaGetSymbolAddress((void**)&pqkv,  g_qkv);
    cudaGetSymbolAddress((void**)&paout, g_aout);
    cudaGetSymbolAddress((void**)&pxn,   g_xn);
    cudaGetSymbolAddress((void**)&ph1,   g_h1);
    cudaGetSymbolAddress((void**)&pbm,   g_bm);

    cudaFuncSetAttribute(tc_gemm<EPI_STORE,1,0>,  cudaFuncAttributeMaxDynamicSharedMemorySize, TC_SMEM);
    cudaFuncSetAttribute(tc_gemm<EPI_PROJLN,0,1>, cudaFuncAttributeMaxDynamicSharedMemorySize, TC_SMEM);
    cudaFuncSetAttribute(tc_gemm<EPI_GELU,0,1>,   cudaFuncAttributeMaxDynamicSharedMemorySize, TC_SMEM);
    cudaFuncSetAttribute(tc_gemm<EPI_RES,0,1>,    cudaFuncAttributeMaxDynamicSharedMemorySize, TC_SMEM);

    const int MB = TOK/128;   // 343 exact
    for (int L = 0; L < 2; L++) {
        int shifted = L & 1;
        const float* xsrc = (L == 0) ? x_in : px;
        bias_prep<<<dim3(NTOK, shifted ? 24 : 3), 128>>>(
            relb + (size_t)L*NBIAS*NHEAD, pbm, shifted);
        tc_gemm<EPI_STORE,1,0><<<dim3(MB, QKVO/96), 256, TC_SMEM>>>(
            xsrc, qkvw + (size_t)L*QKVO*CDIM, qkvb + L*QKVO, pqkv,
            nullptr, nullptr, CDIM, QKVO, shifted,
            n1g + L*CDIM, n1b + L*CDIM, nullptr);
        attn_mma_kernel<<<dim3(BN*NHEAD, 3), 128>>>(pqkv, paout, pbm, shifted);
        tc_gemm<EPI_PROJLN,0,1><<<dim3(MB, 1), 256, TC_SMEM>>>(
            paout, projw + (size_t)L*CDIM*CDIM, projb + L*CDIM, nullptr,
            xsrc, px, CDIM, CDIM, shifted,
            n2g + L*CDIM, n2b + L*CDIM, pxn);
        tc_gemm<EPI_GELU,0,1><<<dim3(MB, FF/96), 256, TC_SMEM>>>(
            pxn, fc1w + (size_t)L*FF*CDIM, fc1b + L*FF, ph1,
            nullptr, nullptr, CDIM, FF, 0,
            nullptr, nullptr, nullptr);
        tc_gemm<EPI_RES,0,1><<<dim3(MB, 1), 256, TC_SMEM>>>(
            ph1, fc2w + (size_t)L*CDIM*FF, fc2b + L*CDIM, (L == 1) ? out : nullptr,
            px, px, FF, CDIM, 0,
            nullptr, nullptr, nullptr);
    }
}